// round 13
// baseline (speedup 1.0000x reference)
#include <cuda_runtime.h>
#include <cuda_bf16.h>
#include <cstdint>
#include <math.h>

#define Bdim   2
#define Ldim   2048
#define DIMV   1024
#define NH     8
#define INNER  128
#define MROWS  (Bdim*Ldim)   /* 4096 */
#define NCAT   (3*DIMV)      /* 3072 */
#define EPSV   1e-5f
#define QMAX   16256.f       /* 127*128 */

// ---------------- scratch (static __device__, no allocs) ----------------
__device__ int8_t g_xa[(size_t)MROWS*DIMV];
__device__ int8_t g_xb[(size_t)MROWS*DIMV];
__device__ int8_t g_wa[(size_t)NCAT*DIMV];
__device__ int8_t g_wb[(size_t)NCAT*DIMV];
__device__ unsigned g_amax[4];                      // [0]=x, [1..3]=Wz,Wza,Wya
__device__ float g_cat[(size_t)MROWS*NCAT];         // raw [lin | act | yact] (48MB)
__device__ float g_spart[MROWS/64][DIMV];
__device__ float g_zrows[Bdim][NH][DIMV];
__device__ float g_lda [Bdim][NH][Ldim];
__device__ float g_Acum[Bdim][NH][Ldim];
__device__ float g_P[Bdim][NH][INNER];
__device__ float g_Q[Bdim][NH][INNER];
__device__ float g_vc[Bdim][NH], g_vt[Bdim][NH], g_cov[Bdim][NH];
__device__ float g_PW[Bdim][NH][DIMV];
__device__ float g_QW[Bdim][NH][DIMV];
__device__ float g_GW[DIMV];

// ================= helpers =================
__device__ __forceinline__ uint32_t smem_u32(const void* p) {
    uint32_t a;
    asm("{ .reg .u64 t; cvta.to.shared.u64 t, %1; cvt.u32.u64 %0, t; }" : "=r"(a) : "l"(p));
    return a;
}
#define SWZ64(o) ((o) ^ (((o) >> 3) & 0x30))

__device__ __forceinline__ void cp16(uint32_t saddr, const void* g) {
    asm volatile("cp.async.cg.shared.global [%0], [%1], 16;" :: "r"(saddr), "l"(g));
}
#define CP_COMMIT()  asm volatile("cp.async.commit_group;" ::: "memory")
#define CP_WAIT0()   asm volatile("cp.async.wait_group 0;" ::: "memory")

__device__ __forceinline__ void ldmx4(uint32_t* r, uint32_t addr) {
    asm volatile("ldmatrix.sync.aligned.m8n8.x4.shared.b16 {%0,%1,%2,%3}, [%4];"
        : "=r"(r[0]), "=r"(r[1]), "=r"(r[2]), "=r"(r[3]) : "r"(addr));
}
__device__ __forceinline__ void mma_s8(int* c, const uint32_t* a, const uint32_t* b) {
    asm volatile(
        "mma.sync.aligned.m16n8k32.row.col.s32.s8.s8.s32 "
        "{%0,%1,%2,%3},{%4,%5,%6,%7},{%8,%9},{%0,%1,%2,%3};"
        : "+r"(c[0]), "+r"(c[1]), "+r"(c[2]), "+r"(c[3])
        : "r"(a[0]), "r"(a[1]), "r"(a[2]), "r"(a[3]), "r"(b[0]), "r"(b[1]));
}

// ================= amax (order-independent -> deterministic) =================
__global__ void kamax_reset() { if (threadIdx.x < 4) g_amax[threadIdx.x] = 0; }

__global__ void kamax(const float* __restrict__ src, int n4, int slot)
{
    int i = blockIdx.x * blockDim.x + threadIdx.x;
    int stride = gridDim.x * blockDim.x;
    float m = 0.f;
    for (; i < n4; i += stride) {
        float4 v = ((const float4*)src)[i];
        m = fmaxf(m, fmaxf(fmaxf(fabsf(v.x), fabsf(v.y)), fmaxf(fabsf(v.z), fabsf(v.w))));
    }
    for (int off = 16; off; off >>= 1) m = fmaxf(m, __shfl_xor_sync(0xffffffffu, m, off));
    __shared__ float sm[8];
    if ((threadIdx.x & 31) == 0) sm[threadIdx.x >> 5] = m;
    __syncthreads();
    if (threadIdx.x == 0) {
        float bm = 0.f;
        for (int w = 0; w < (int)(blockDim.x >> 5); w++) bm = fmaxf(bm, sm[w]);
        atomicMax(&g_amax[slot], __float_as_uint(bm));
    }
}

// ================= quantize: fp32 -> (a,b) int8 pair, v ~ (128a+b)/s =================
__global__ void kquant(const float* __restrict__ src, int8_t* __restrict__ qa,
                       int8_t* __restrict__ qb, int n4, int slot)
{
    int i = blockIdx.x * blockDim.x + threadIdx.x;
    if (i >= n4) return;
    float s = QMAX / __uint_as_float(g_amax[slot]);
    float4 v = ((const float4*)src)[i];
    int q0 = __float2int_rn(v.x * s), q1 = __float2int_rn(v.y * s);
    int q2 = __float2int_rn(v.z * s), q3 = __float2int_rn(v.w * s);
    int a0 = (q0 + 64) >> 7, a1 = (q1 + 64) >> 7, a2 = (q2 + 64) >> 7, a3 = (q3 + 64) >> 7;
    int b0 = q0 - (a0 << 7), b1 = q1 - (a1 << 7), b2 = q2 - (a2 << 7), b3 = q3 - (a3 << 7);
    ((char4*)qa)[i] = make_char4((char)a0, (char)a1, (char)a2, (char)a3);
    ((char4*)qb)[i] = make_char4((char)b0, (char)b1, (char)b2, (char)b3);
}

// ================= GEMM: C[4096x3072] = X @ Wcat^T, int8 IMMA hi/lo =================
// BM=128, BN=128, BK=64 (bytes). 256 threads = 8 warps (4m x 2n), warp tile 32x64.
#define OFF_XA 0
#define OFF_XB 8192
#define OFF_WA 16384
#define OFF_WB 24576
#define STG    32768
#define GEMM_SMEM (2*STG)

__global__ void __launch_bounds__(256, 1)
kgemm_i8()
{
    extern __shared__ char smem[];
    const uint32_t sb = smem_u32(smem);
    const int tid = threadIdx.x;
    const int wid = tid >> 5, lane = tid & 31;
    const int wm = wid >> 1, wn = wid & 1;
    const int n0 = blockIdx.x * 128;
    const int r0 = blockIdx.y * 128;

    int aa[2][8][4], cx[2][8][4];
#pragma unroll
    for (int m = 0; m < 2; m++)
#pragma unroll
        for (int n = 0; n < 8; n++)
#pragma unroll
            for (int c = 0; c < 4; c++) { aa[m][n][c] = 0; cx[m][n][c] = 0; }

    // stage loader: 2048 x 16B chunks (rows of 64 bytes = K-window 64)
    auto load_stage = [&](int stage, int kt) {
        uint32_t base = sb + stage * STG;
        int k0 = kt * 64;
#pragma unroll
        for (int u = 0; u < 8; u++) {
            int i = tid + u * 256;
            int mat = i >> 9;                       // 0:XA 1:XB 2:WA 3:WB
            int idx = i & 511;
            int row = idx >> 2, c = idx & 3;
            uint32_t so = SWZ64((uint32_t)(row*64 + c*16));
            uint32_t dst = base + mat*8192 + so;
            const int8_t* src;
            if (mat == 0)      src = g_xa + (size_t)(r0+row)*DIMV + k0 + c*16;
            else if (mat == 1) src = g_xb + (size_t)(r0+row)*DIMV + k0 + c*16;
            else if (mat == 2) src = g_wa + (size_t)(n0+row)*DIMV + k0 + c*16;
            else               src = g_wb + (size_t)(n0+row)*DIMV + k0 + c*16;
            cp16(dst, src);
        }
    };

    load_stage(0, 0);
    CP_COMMIT();

    for (int it = 0; it < 16; it++) {
        CP_WAIT0();
        __syncthreads();
        if (it + 1 < 16) { load_stage((it+1) & 1, it+1); CP_COMMIT(); }

        uint32_t stg = sb + (it & 1) * STG;
#pragma unroll
        for (int kh = 0; kh < 2; kh++) {            // two k32 chunks per stage
            // A fragments (hi a, lo b): 2 m16 tiles each
            uint32_t xa2[2][4], xb2[2][4];
#pragma unroll
            for (int m = 0; m < 2; m++) {
                int row = wm*32 + m*16 + (lane & 15);
                uint32_t so = SWZ64((uint32_t)(row*64 + kh*32 + (lane >> 4)*16));
                ldmx4(xa2[m], stg + OFF_XA + so);
                ldmx4(xb2[m], stg + OFF_XB + so);
            }
            // B tiles: 4 pairs of n8; consume immediately (keeps regs low)
#pragma unroll
            for (int p = 0; p < 4; p++) {
                int row = wn*64 + p*16 + (lane & 7) + ((lane >> 4) & 1) * 8;
                uint32_t so = SWZ64((uint32_t)(row*64 + kh*32 + ((lane >> 3) & 1)*16));
                uint32_t wa_t[4], wb_t[4];
                ldmx4(wa_t, stg + OFF_WA + so);
                ldmx4(wb_t, stg + OFF_WB + so);
#pragma unroll
                for (int m = 0; m < 2; m++) {
                    mma_s8(aa[m][2*p],   xa2[m], &wa_t[0]);
                    mma_s8(cx[m][2*p],   xa2[m], &wb_t[0]);
                    mma_s8(cx[m][2*p],   xb2[m], &wa_t[0]);
                    mma_s8(aa[m][2*p+1], xa2[m], &wa_t[2]);
                    mma_s8(cx[m][2*p+1], xa2[m], &wb_t[2]);
                    mma_s8(cx[m][2*p+1], xb2[m], &wa_t[2]);
                }
            }
        }
        __syncthreads();
    }

    // ---- epilogue: combine scales, write float to g_cat ----
    int mat = n0 >> 10;
    float inv = (__uint_as_float(g_amax[0]) * __uint_as_float(g_amax[1 + mat]))
              / (QMAX * QMAX);
#pragma unroll
    for (int m = 0; m < 2; m++) {
        int rowA = r0 + wm*32 + m*16 + (lane >> 2);
#pragma unroll
        for (int n = 0; n < 8; n++) {
            int col = n0 + wn*64 + n*8 + (lane & 3)*2;
            float2 v0, v1;
            v0.x = fmaf(16384.f, (float)aa[m][n][0], 128.f*(float)cx[m][n][0]) * inv;
            v0.y = fmaf(16384.f, (float)aa[m][n][1], 128.f*(float)cx[m][n][1]) * inv;
            v1.x = fmaf(16384.f, (float)aa[m][n][2], 128.f*(float)cx[m][n][2]) * inv;
            v1.y = fmaf(16384.f, (float)aa[m][n][3], 128.f*(float)cx[m][n][3]) * inv;
            *(float2*)(g_cat + (size_t)rowA*NCAT + col)     = v0;
            *(float2*)(g_cat + (size_t)(rowA+8)*NCAT + col) = v1;
        }
    }
}

// ================= K2e: z = (lin+bz)*silu(act+bza); colsums; zrows =================
__global__ void k2e_epi(const float* __restrict__ bz, const float* __restrict__ bza)
{
    int jc = blockIdx.x * 256 + threadIdx.x;      // 0..1023
    int rt = blockIdx.y;                          // 0..63
    int h  = jc >> 7;
    float bzv = bz[jc], bzav = bza[jc];
    float s = 0.f;
    int rbase = rt * 64;
    int b = rbase >> 11;
#pragma unroll 4
    for (int i = 0; i < 64; i++) {
        int r = rbase + i;
        int l = r & (Ldim-1);
        float lin = g_cat[(size_t)r*NCAT + jc] + bzv;
        float a   = g_cat[(size_t)r*NCAT + DIMV + jc] + bzav;
        float zv  = lin * (a / (1.f + expf(-a)));
        if (l > h) s += zv;
        if (l < NH) g_zrows[b][l][jc] = zv;
    }
    g_spart[rt][jc] = s;
}

// ================= K1a: dt projection (warp per row) =================
__global__ void k1_dt(const float* __restrict__ x, const float* __restrict__ Wdt,
                      const float* __restrict__ bdt, const float* __restrict__ lna)
{
    int gw   = (blockIdx.x * blockDim.x + threadIdx.x) >> 5;
    int lane = threadIdx.x & 31;
    if (gw >= MROWS) return;
    const float* xr = x + (size_t)gw * DIMV;
    float acc[NH];
#pragma unroll
    for (int h = 0; h < NH; h++) acc[h] = 0.f;
    for (int k = lane; k < DIMV; k += 32) {
        float xv = xr[k];
#pragma unroll
        for (int h = 0; h < NH; h++) acc[h] += xv * Wdt[h*DIMV + k];
    }
#pragma unroll
    for (int h = 0; h < NH; h++)
        for (int off = 16; off; off >>= 1)
            acc[h] += __shfl_xor_sync(0xffffffffu, acc[h], off);
    if (lane == 0) {
        int b = gw >> 11, l = gw & (Ldim-1);
#pragma unroll
        for (int h = 0; h < NH; h++) {
            float v  = acc[h] + bdt[h];
            float sp = fmaxf(v, 0.f) + log1pf(expf(-fabsf(v)));
            g_lda[b][h][l] = -expf(lna[h]) * sp;
        }
    }
}

// ================= K1b: inclusive scan + exp =================
__global__ void k1b_scan()
{
    int b = blockIdx.x >> 3, h = blockIdx.x & 7;
    int t = threadIdx.x;
    const float* src = g_lda[b][h];
    int base = t * 8;
    float v[8]; float s = 0.f;
#pragma unroll
    for (int u = 0; u < 8; u++) { v[u] = src[base+u]; s += v[u]; }
    __shared__ float sm[256];
    sm[t] = s; __syncthreads();
    for (int d = 1; d < 256; d <<= 1) {
        float add = (t >= d) ? sm[t-d] : 0.f;
        __syncthreads();
        sm[t] += add;
        __syncthreads();
    }
    float run = sm[t] - s;
#pragma unroll
    for (int u = 0; u < 8; u++) { run += v[u]; g_Acum[b][h][base+u] = expf(run); }
}

// ================= K3: per-(b,h) stats =================
__device__ __forceinline__ float blockSum128(float v, float* sm)
{
    for (int off = 16; off; off >>= 1) v += __shfl_xor_sync(0xffffffffu, v, off);
    int w = threadIdx.x >> 5;
    if ((threadIdx.x & 31) == 0) sm[w] = v;
    __syncthreads();
    float r = sm[0] + sm[1] + sm[2] + sm[3];
    __syncthreads();
    return r;
}

__global__ void k3_stats(const float* __restrict__ hidden, const float* __restrict__ gnw,
                         float* __restrict__ out, int writeHidden)
{
    int b = blockIdx.x >> 3, h = blockIdx.x & 7;
    int i = threadIdx.x;
    int col = h*INNER + i;
    float S = 0.f;
#pragma unroll 8
    for (int t = 0; t < MROWS/64/Bdim; t++)
        S += g_spart[b*(MROWS/64/Bdim) + t][col];
    float c  = g_zrows[b][h][col];
    float tv = S + hidden[(b*NH+h)*INNER + i];

    __shared__ float sm[4];
    float mc = blockSum128(c,  sm) * (1.f/INNER);
    float mt = blockSum128(tv, sm) * (1.f/INNER);
    float dc = c - mc, dq = tv - mt;
    float vc = blockSum128(dc*dc, sm) * (1.f/INNER);
    float vt = blockSum128(dq*dq, sm) * (1.f/INNER);
    float cv = blockSum128(dc*dq, sm) * (1.f/INNER);
    if (i == 0) { g_vc[b][h]=vc; g_vt[b][h]=vt; g_cov[b][h]=cv; }
    float w = gnw[h];
    g_P[b][h][i] = dc * w;
    g_Q[b][h][i] = dq * w;
    if (writeHidden)
        out[(size_t)MROWS*DIMV + (b*NH+h)*INNER + i] = c + g_Acum[b][h][Ldim-1]*tv;
}

// ================= K4: rank-16 projections through W_y =================
__global__ void k4_proj(const float* __restrict__ Wy, const float* __restrict__ by,
                        const float* __restrict__ gnb)
{
    __shared__ float Ps[Bdim*NH*INNER];
    __shared__ float Qs[Bdim*NH*INNER];
    for (int idx = threadIdx.x; idx < Bdim*NH*INNER; idx += blockDim.x) {
        Ps[idx] = ((const float*)g_P)[idx];
        Qs[idx] = ((const float*)g_Q)[idx];
    }
    __syncthreads();
    int j    = (blockIdx.x * blockDim.x + threadIdx.x) >> 5;
    int lane = threadIdx.x & 31;
    if (j >= DIMV) return;
    const float* wrow = Wy + (size_t)j*DIMV;
    float gb = 0.f;
#pragma unroll
    for (int h = 0; h < NH; h++) {
        float aP0=0.f, aQ0=0.f, aP1=0.f, aQ1=0.f, aW=0.f;
#pragma unroll
        for (int kk = 0; kk < 4; kk++) {
            int ii = kk*32 + lane;
            float w = wrow[h*INNER + ii];
            aW  += w;
            aP0 += w * Ps[(0*NH+h)*INNER + ii];
            aQ0 += w * Qs[(0*NH+h)*INNER + ii];
            aP1 += w * Ps[(1*NH+h)*INNER + ii];
            aQ1 += w * Qs[(1*NH+h)*INNER + ii];
        }
        for (int off = 16; off; off >>= 1) {
            aP0 += __shfl_xor_sync(0xffffffffu, aP0, off);
            aQ0 += __shfl_xor_sync(0xffffffffu, aQ0, off);
            aP1 += __shfl_xor_sync(0xffffffffu, aP1, off);
            aQ1 += __shfl_xor_sync(0xffffffffu, aQ1, off);
            aW  += __shfl_xor_sync(0xffffffffu, aW,  off);
        }
        if (lane == 0) {
            g_PW[0][h][j] = aP0;  g_QW[0][h][j] = aQ0;
            g_PW[1][h][j] = aP1;  g_QW[1][h][j] = aQ1;
            gb += gnb[h] * aW;
        }
    }
    if (lane == 0) g_GW[j] = by[j] + gb;
}

// ================= K5: final combine =================
__global__ void k5_final(float* __restrict__ out, const float* __restrict__ bya)
{
    int r = blockIdx.x;
    int b = r >> 11, l = r & (Ldim-1);
    __shared__ float cP[NH], cQ[NH];
    if (threadIdx.x < NH) {
        int h = threadIdx.x;
        float A   = g_Acum[b][h][l];
        float var = g_vc[b][h] + 2.f*A*g_cov[b][h] + A*A*g_vt[b][h];
        float inv = rsqrtf(var + EPSV);
        cP[h] = inv;
        cQ[h] = A * inv;
    }
    __syncthreads();
    for (int j = threadIdx.x; j < DIMV; j += blockDim.x) {
        float y0 = g_GW[j];
#pragma unroll
        for (int h = 0; h < NH; h++)
            y0 += cP[h]*g_PW[b][h][j] + cQ[h]*g_QW[b][h][j];
        float ya = g_cat[(size_t)r*NCAT + 2*DIMV + j] + bya[j];
        out[(size_t)r*DIMV + j] = y0 * (ya / (1.f + expf(-ya)));
    }
}

// ================= launch =================
extern "C" void kernel_launch(void* const* d_in, const int* in_sizes, int n_in,
                              void* d_out, int out_size)
{
    const float* x    = (const float*)d_in[0];
    const float* hid  = (const float*)d_in[1];
    const float* W_z  = (const float*)d_in[2];
    const float* b_z  = (const float*)d_in[3];
    const float* W_za = (const float*)d_in[4];
    const float* b_za = (const float*)d_in[5];
    const float* W_y  = (const float*)d_in[6];
    const float* b_y  = (const float*)d_in[7];
    const float* W_ya = (const float*)d_in[8];
    const float* b_ya = (const float*)d_in[9];
    const float* W_dt = (const float*)d_in[10];
    const float* b_dt = (const float*)d_in[11];
    const float* ln_a = (const float*)d_in[12];
    const float* gn_w = (const float*)d_in[13];
    const float* gn_b = (const float*)d_in[14];
    float* out = (float*)d_out;
    int writeHidden = (out_size >= MROWS*DIMV + Bdim*NH*INNER) ? 1 : 0;

    cudaFuncSetAttribute(kgemm_i8, cudaFuncAttributeMaxDynamicSharedMemorySize, GEMM_SMEM);

    int8_t *xa, *xb, *wa, *wb;
    cudaGetSymbolAddress((void**)&xa, g_xa);
    cudaGetSymbolAddress((void**)&xb, g_xb);
    cudaGetSymbolAddress((void**)&wa, g_wa);
    cudaGetSymbolAddress((void**)&wb, g_wb);

    const int NX4 = MROWS*DIMV/4;   // 1M
    const int NW4 = DIMV*DIMV/4;    // 256K

    kamax_reset<<<1, 32>>>();
    kamax<<<512, 256>>>(x,    NX4, 0);
    kamax<<<256, 256>>>(W_z,  NW4, 1);
    kamax<<<256, 256>>>(W_za, NW4, 2);
    kamax<<<256, 256>>>(W_ya, NW4, 3);

    kquant<<<(NX4 + 255)/256, 256>>>(x,    xa,               xb,               NX4, 0);
    kquant<<<(NW4 + 255)/256, 256>>>(W_z,  wa,               wb,               NW4, 1);
    kquant<<<(NW4 + 255)/256, 256>>>(W_za, wa + DIMV*DIMV,   wb + DIMV*DIMV,   NW4, 2);
    kquant<<<(NW4 + 255)/256, 256>>>(W_ya, wa + 2*DIMV*DIMV, wb + 2*DIMV*DIMV, NW4, 3);

    k1_dt  <<<MROWS/8, 256>>>(x, W_dt, b_dt, ln_a);
    k1b_scan<<<Bdim*NH, 256>>>();

    dim3 gg(NCAT/128, MROWS/128);
    kgemm_i8<<<gg, 256, GEMM_SMEM>>>();

    dim3 ge(DIMV/256, MROWS/64);
    k2e_epi<<<ge, 256>>>(b_z, b_za);

    k3_stats<<<Bdim*NH, INNER>>>(hid, gn_w, out, writeHidden);
    k4_proj<<<DIMV/8, 256>>>(W_y, b_y, gn_b);
    k5_final<<<MROWS, 256>>>(out, b_ya);
}

// round 14
// speedup vs baseline: 4.0612x; 4.0612x over previous
#include <cuda_runtime.h>
#include <cuda_fp16.h>
#include <cstdint>
#include <math.h>

#define Bdim   2
#define Ldim   2048
#define DIMV   1024
#define NH     8
#define INNER  128
#define MROWS  (Bdim*Ldim)   /* 4096 */
#define NCAT   (3*DIMV)      /* 3072 */
#define EPSV   1e-5f

// ---------------- scratch (static __device__, no allocs) ----------------
__device__ __half g_xf[(size_t)MROWS*DIMV];
__device__ __half g_wf[(size_t)NCAT*DIMV];
__device__ float g_cat[(size_t)MROWS*NCAT];         // raw [lin | act | yact] (48MB)
__device__ float g_spart[MROWS/64][DIMV];
__device__ float g_zrows[Bdim][NH][DIMV];
__device__ float g_lda [Bdim][NH][Ldim];
__device__ float g_Acum[Bdim][NH][Ldim];
__device__ float g_P[Bdim][NH][INNER];
__device__ float g_Q[Bdim][NH][INNER];
__device__ float g_vc[Bdim][NH], g_vt[Bdim][NH], g_cov[Bdim][NH];
__device__ float g_PW[Bdim][NH][DIMV];
__device__ float g_QW[Bdim][NH][DIMV];
__device__ float g_GW[DIMV];

// ================= helpers =================
__device__ __forceinline__ uint32_t smem_u32(const void* p) {
    uint32_t a;
    asm("{ .reg .u64 t; cvta.to.shared.u64 t, %1; cvt.u32.u64 %0, t; }" : "=r"(a) : "l"(p));
    return a;
}
#define SWZ64(o) ((o) ^ (((o) >> 3) & 0x30))

__device__ __forceinline__ void cp16(uint32_t saddr, const void* g) {
    asm volatile("cp.async.cg.shared.global [%0], [%1], 16;" :: "r"(saddr), "l"(g));
}
#define CP_COMMIT()  asm volatile("cp.async.commit_group;" ::: "memory")
#define CP_WAIT0()   asm volatile("cp.async.wait_group 0;" ::: "memory")

__device__ __forceinline__ void ldmx4(uint32_t* r, uint32_t addr) {
    asm volatile("ldmatrix.sync.aligned.m8n8.x4.shared.b16 {%0,%1,%2,%3}, [%4];"
        : "=r"(r[0]), "=r"(r[1]), "=r"(r[2]), "=r"(r[3]) : "r"(addr));
}
__device__ __forceinline__ void mma_f16(float* c, const uint32_t* a, const uint32_t* b) {
    asm volatile(
        "mma.sync.aligned.m16n8k16.row.col.f32.f16.f16.f32 "
        "{%0,%1,%2,%3},{%4,%5,%6,%7},{%8,%9},{%0,%1,%2,%3};"
        : "+f"(c[0]), "+f"(c[1]), "+f"(c[2]), "+f"(c[3])
        : "r"(a[0]), "r"(a[1]), "r"(a[2]), "r"(a[3]), "r"(b[0]), "r"(b[1]));
}

// ================= K0: fp32 -> fp16 =================
__global__ void kconv_h(const float* __restrict__ src, __half* __restrict__ dst, int n4)
{
    int i = blockIdx.x * blockDim.x + threadIdx.x;
    if (i >= n4) return;
    float4 v = ((const float4*)src)[i];
    __half2 p0 = make_half2(__float2half(v.x), __float2half(v.y));
    __half2 p1 = make_half2(__float2half(v.z), __float2half(v.w));
    uint2 o;
    o.x = *(uint32_t*)&p0;
    o.y = *(uint32_t*)&p1;
    ((uint2*)dst)[i] = o;
}

// ================= GEMM: C[4096x3072] = X @ Wcat^T, fp16 mma =================
// BM=128, BN=256, BK=32. 512 threads = 16 warps (4m x 4n), warp tile 32x64.
#define OFF_A  0
#define OFF_B  8192
#define STG    24576          /* A 8KB + B 16KB */
#define GEMM_SMEM (2*STG)

__global__ void __launch_bounds__(512, 1)
kgemm_h()
{
    extern __shared__ char smem[];
    const uint32_t sb = smem_u32(smem);
    const int tid = threadIdx.x;
    const int wid = tid >> 5, lane = tid & 31;
    const int wm = wid >> 2, wn = wid & 3;          // 4 x 4 warps
    const int n0 = blockIdx.x * 256;
    const int r0 = blockIdx.y * 128;

    float acc[2][8][4];
#pragma unroll
    for (int m = 0; m < 2; m++)
#pragma unroll
        for (int n = 0; n < 8; n++)
#pragma unroll
            for (int c = 0; c < 4; c++) acc[m][n][c] = 0.f;

    // stage loader: 1536 x 16B chunks (A: 512, B: 1024); rows of 64B (32 halves)
    auto load_stage = [&](int stage, int kt) {
        uint32_t base = sb + stage * STG;
        int k0 = kt * 32;
#pragma unroll
        for (int u = 0; u < 3; u++) {
            int i = tid + u * 512;                  // 0..1535
            uint32_t so, dst;
            const __half* src;
            if (i < 512) {
                int row = i >> 2, c = i & 3;
                so  = SWZ64((uint32_t)(row*64 + c*16));
                dst = base + OFF_A + so;
                src = g_xf + (size_t)(r0+row)*DIMV + k0 + c*8;
            } else {
                int idx = i - 512;
                int row = idx >> 2, c = idx & 3;
                so  = SWZ64((uint32_t)(row*64 + c*16));
                dst = base + OFF_B + so;
                src = g_wf + (size_t)(n0+row)*DIMV + k0 + c*8;
            }
            cp16(dst, src);
        }
    };

    load_stage(0, 0);
    CP_COMMIT();

    for (int it = 0; it < 32; it++) {
        CP_WAIT0();
        __syncthreads();
        if (it + 1 < 32) { load_stage((it+1) & 1, it+1); CP_COMMIT(); }

        uint32_t stg = sb + (it & 1) * STG;
#pragma unroll
        for (int kh = 0; kh < 2; kh++) {            // two k16 halves per stage
            uint32_t af[2][4];
#pragma unroll
            for (int m = 0; m < 2; m++) {
                int row = wm*32 + m*16 + (lane & 15);
                uint32_t so = SWZ64((uint32_t)(row*64 + (kh*2 + (lane >> 4))*16));
                ldmx4(af[m], stg + OFF_A + so);
            }
#pragma unroll
            for (int p = 0; p < 4; p++) {
                int row = wn*64 + p*16 + (lane & 7) + ((lane >> 4) & 1) * 8;
                uint32_t so = SWZ64((uint32_t)(row*64 + (kh*2 + ((lane >> 3) & 1))*16));
                uint32_t bt[4];
                ldmx4(bt, stg + OFF_B + so);
#pragma unroll
                for (int m = 0; m < 2; m++) {
                    mma_f16(acc[m][2*p],   af[m], &bt[0]);
                    mma_f16(acc[m][2*p+1], af[m], &bt[2]);
                }
            }
        }
        __syncthreads();
    }

    // ---- epilogue: write float to g_cat ----
#pragma unroll
    for (int m = 0; m < 2; m++) {
        int rowA = r0 + wm*32 + m*16 + (lane >> 2);
#pragma unroll
        for (int n = 0; n < 8; n++) {
            int col = n0 + wn*64 + n*8 + (lane & 3)*2;
            *(float2*)(g_cat + (size_t)rowA*NCAT + col)     = make_float2(acc[m][n][0], acc[m][n][1]);
            *(float2*)(g_cat + (size_t)(rowA+8)*NCAT + col) = make_float2(acc[m][n][2], acc[m][n][3]);
        }
    }
}

// ================= K2e: z = (lin+bz)*silu(act+bza); colsums; zrows =================
__global__ void k2e_epi(const float* __restrict__ bz, const float* __restrict__ bza)
{
    int jc = blockIdx.x * 256 + threadIdx.x;      // 0..1023
    int rt = blockIdx.y;                          // 0..63
    int h  = jc >> 7;
    float bzv = bz[jc], bzav = bza[jc];
    float s = 0.f;
    int rbase = rt * 64;
    int b = rbase >> 11;
#pragma unroll 4
    for (int i = 0; i < 64; i++) {
        int r = rbase + i;
        int l = r & (Ldim-1);
        float lin = g_cat[(size_t)r*NCAT + jc] + bzv;
        float a   = g_cat[(size_t)r*NCAT + DIMV + jc] + bzav;
        float zv  = lin * (a / (1.f + expf(-a)));
        if (l > h) s += zv;
        if (l < NH) g_zrows[b][l][jc] = zv;
    }
    g_spart[rt][jc] = s;
}

// ================= K1a: dt projection (warp per row) =================
__global__ void k1_dt(const float* __restrict__ x, const float* __restrict__ Wdt,
                      const float* __restrict__ bdt, const float* __restrict__ lna)
{
    int gw   = (blockIdx.x * blockDim.x + threadIdx.x) >> 5;
    int lane = threadIdx.x & 31;
    if (gw >= MROWS) return;
    const float* xr = x + (size_t)gw * DIMV;
    float acc[NH];
#pragma unroll
    for (int h = 0; h < NH; h++) acc[h] = 0.f;
    for (int k = lane; k < DIMV; k += 32) {
        float xv = xr[k];
#pragma unroll
        for (int h = 0; h < NH; h++) acc[h] += xv * Wdt[h*DIMV + k];
    }
#pragma unroll
    for (int h = 0; h < NH; h++)
        for (int off = 16; off; off >>= 1)
            acc[h] += __shfl_xor_sync(0xffffffffu, acc[h], off);
    if (lane == 0) {
        int b = gw >> 11, l = gw & (Ldim-1);
#pragma unroll
        for (int h = 0; h < NH; h++) {
            float v  = acc[h] + bdt[h];
            float sp = fmaxf(v, 0.f) + log1pf(expf(-fabsf(v)));
            g_lda[b][h][l] = -expf(lna[h]) * sp;
        }
    }
}

// ================= K1b: inclusive scan + exp =================
__global__ void k1b_scan()
{
    int b = blockIdx.x >> 3, h = blockIdx.x & 7;
    int t = threadIdx.x;
    const float* src = g_lda[b][h];
    int base = t * 8;
    float v[8]; float s = 0.f;
#pragma unroll
    for (int u = 0; u < 8; u++) { v[u] = src[base+u]; s += v[u]; }
    __shared__ float sm[256];
    sm[t] = s; __syncthreads();
    for (int d = 1; d < 256; d <<= 1) {
        float add = (t >= d) ? sm[t-d] : 0.f;
        __syncthreads();
        sm[t] += add;
        __syncthreads();
    }
    float run = sm[t] - s;
#pragma unroll
    for (int u = 0; u < 8; u++) { run += v[u]; g_Acum[b][h][base+u] = expf(run); }
}

// ================= K3: per-(b,h) stats =================
__device__ __forceinline__ float blockSum128(float v, float* sm)
{
    for (int off = 16; off; off >>= 1) v += __shfl_xor_sync(0xffffffffu, v, off);
    int w = threadIdx.x >> 5;
    if ((threadIdx.x & 31) == 0) sm[w] = v;
    __syncthreads();
    float r = sm[0] + sm[1] + sm[2] + sm[3];
    __syncthreads();
    return r;
}

__global__ void k3_stats(const float* __restrict__ hidden, const float* __restrict__ gnw,
                         float* __restrict__ out, int writeHidden)
{
    int b = blockIdx.x >> 3, h = blockIdx.x & 7;
    int i = threadIdx.x;
    int col = h*INNER + i;
    float S = 0.f;
#pragma unroll 8
    for (int t = 0; t < MROWS/64/Bdim; t++)
        S += g_spart[b*(MROWS/64/Bdim) + t][col];
    float c  = g_zrows[b][h][col];
    float tv = S + hidden[(b*NH+h)*INNER + i];

    __shared__ float sm[4];
    float mc = blockSum128(c,  sm) * (1.f/INNER);
    float mt = blockSum128(tv, sm) * (1.f/INNER);
    float dc = c - mc, dq = tv - mt;
    float vc = blockSum128(dc*dc, sm) * (1.f/INNER);
    float vt = blockSum128(dq*dq, sm) * (1.f/INNER);
    float cv = blockSum128(dc*dq, sm) * (1.f/INNER);
    if (i == 0) { g_vc[b][h]=vc; g_vt[b][h]=vt; g_cov[b][h]=cv; }
    float w = gnw[h];
    g_P[b][h][i] = dc * w;
    g_Q[b][h][i] = dq * w;
    if (writeHidden)
        out[(size_t)MROWS*DIMV + (b*NH+h)*INNER + i] = c + g_Acum[b][h][Ldim-1]*tv;
}

// ================= K4: rank-16 projections through W_y =================
__global__ void k4_proj(const float* __restrict__ Wy, const float* __restrict__ by,
                        const float* __restrict__ gnb)
{
    __shared__ float Ps[Bdim*NH*INNER];
    __shared__ float Qs[Bdim*NH*INNER];
    for (int idx = threadIdx.x; idx < Bdim*NH*INNER; idx += blockDim.x) {
        Ps[idx] = ((const float*)g_P)[idx];
        Qs[idx] = ((const float*)g_Q)[idx];
    }
    __syncthreads();
    int j    = (blockIdx.x * blockDim.x + threadIdx.x) >> 5;
    int lane = threadIdx.x & 31;
    if (j >= DIMV) return;
    const float* wrow = Wy + (size_t)j*DIMV;
    float gb = 0.f;
#pragma unroll
    for (int h = 0; h < NH; h++) {
        float aP0=0.f, aQ0=0.f, aP1=0.f, aQ1=0.f, aW=0.f;
#pragma unroll
        for (int kk = 0; kk < 4; kk++) {
            int ii = kk*32 + lane;
            float w = wrow[h*INNER + ii];
            aW  += w;
            aP0 += w * Ps[(0*NH+h)*INNER + ii];
            aQ0 += w * Qs[(0*NH+h)*INNER + ii];
            aP1 += w * Ps[(1*NH+h)*INNER + ii];
            aQ1 += w * Qs[(1*NH+h)*INNER + ii];
        }
        for (int off = 16; off; off >>= 1) {
            aP0 += __shfl_xor_sync(0xffffffffu, aP0, off);
            aQ0 += __shfl_xor_sync(0xffffffffu, aQ0, off);
            aP1 += __shfl_xor_sync(0xffffffffu, aP1, off);
            aQ1 += __shfl_xor_sync(0xffffffffu, aQ1, off);
            aW  += __shfl_xor_sync(0xffffffffu, aW,  off);
        }
        if (lane == 0) {
            g_PW[0][h][j] = aP0;  g_QW[0][h][j] = aQ0;
            g_PW[1][h][j] = aP1;  g_QW[1][h][j] = aQ1;
            gb += gnb[h] * aW;
        }
    }
    if (lane == 0) g_GW[j] = by[j] + gb;
}

// ================= K5: final combine =================
__global__ void k5_final(float* __restrict__ out, const float* __restrict__ bya)
{
    int r = blockIdx.x;
    int b = r >> 11, l = r & (Ldim-1);
    __shared__ float cP[NH], cQ[NH];
    if (threadIdx.x < NH) {
        int h = threadIdx.x;
        float A   = g_Acum[b][h][l];
        float var = g_vc[b][h] + 2.f*A*g_cov[b][h] + A*A*g_vt[b][h];
        float inv = rsqrtf(var + EPSV);
        cP[h] = inv;
        cQ[h] = A * inv;
    }
    __syncthreads();
    for (int j = threadIdx.x; j < DIMV; j += blockDim.x) {
        float y0 = g_GW[j];
#pragma unroll
        for (int h = 0; h < NH; h++)
            y0 += cP[h]*g_PW[b][h][j] + cQ[h]*g_QW[b][h][j];
        float ya = g_cat[(size_t)r*NCAT + 2*DIMV + j] + bya[j];
        out[(size_t)r*DIMV + j] = y0 * (ya / (1.f + expf(-ya)));
    }
}

// ================= launch =================
extern "C" void kernel_launch(void* const* d_in, const int* in_sizes, int n_in,
                              void* d_out, int out_size)
{
    const float* x    = (const float*)d_in[0];
    const float* hid  = (const float*)d_in[1];
    const float* W_z  = (const float*)d_in[2];
    const float* b_z  = (const float*)d_in[3];
    const float* W_za = (const float*)d_in[4];
    const float* b_za = (const float*)d_in[5];
    const float* W_y  = (const float*)d_in[6];
    const float* b_y  = (const float*)d_in[7];
    const float* W_ya = (const float*)d_in[8];
    const float* b_ya = (const float*)d_in[9];
    const float* W_dt = (const float*)d_in[10];
    const float* b_dt = (const float*)d_in[11];
    const float* ln_a = (const float*)d_in[12];
    const float* gn_w = (const float*)d_in[13];
    const float* gn_b = (const float*)d_in[14];
    float* out = (float*)d_out;
    int writeHidden = (out_size >= MROWS*DIMV + Bdim*NH*INNER) ? 1 : 0;

    cudaFuncSetAttribute(kgemm_h, cudaFuncAttributeMaxDynamicSharedMemorySize, GEMM_SMEM);

    __half *xf, *wf;
    cudaGetSymbolAddress((void**)&xf, g_xf);
    cudaGetSymbolAddress((void**)&wf, g_wf);

    const int NX4 = MROWS*DIMV/4;   // 1M
    const int NW4 = DIMV*DIMV/4;    // 256K

    kconv_h<<<(NX4 + 255)/256, 256>>>(x,    xf,               NX4);
    kconv_h<<<(NW4 + 255)/256, 256>>>(W_z,  wf,               NW4);
    kconv_h<<<(NW4 + 255)/256, 256>>>(W_za, wf + DIMV*DIMV,   NW4);
    kconv_h<<<(NW4 + 255)/256, 256>>>(W_ya, wf + 2*DIMV*DIMV, NW4);

    k1_dt<<<MROWS/8, 256>>>(x, W_dt, b_dt, ln_a);

    dim3 gg(NCAT/256, MROWS/128);
    kgemm_h<<<gg, 512, GEMM_SMEM>>>();

    k1b_scan<<<Bdim*NH, 256>>>();

    dim3 ge(DIMV/256, MROWS/64);
    k2e_epi<<<ge, 256>>>(b_z, b_za);

    k3_stats<<<Bdim*NH, INNER>>>(hid, gn_w, out, writeHidden);
    k4_proj<<<DIMV/8, 256>>>(W_y, b_y, gn_b);
    k5_final<<<MROWS, 256>>>(out, b_ya);
}

// round 15
// speedup vs baseline: 5.0951x; 1.2546x over previous
#include <cuda_runtime.h>
#include <cuda_fp16.h>
#include <cstdint>
#include <math.h>

#define Bdim   2
#define Ldim   2048
#define DIMV   1024
#define NH     8
#define INNER  128
#define MROWS  (Bdim*Ldim)   /* 4096 */
#define EPSV   1e-5f

// ---------------- scratch (static __device__, no allocs) ----------------
__device__ __half g_xf[(size_t)MROWS*DIMV];
__device__ __half g_wzi[(size_t)2048*DIMV];         // interleaved rows: 2j=Wz[j], 2j+1=Wza[j]
__device__ __half g_wy[(size_t)DIMV*DIMV];          // Wya
__device__ float g_yact[(size_t)MROWS*DIMV];        // x @ Wya^T (16MB)
__device__ float g_spart[MROWS/128][DIMV];          // per-128-row-tile masked colsums of z
__device__ float g_zrows[Bdim][NH][DIMV];
__device__ float g_lda [Bdim][NH][Ldim];
__device__ float g_Acum[Bdim][NH][Ldim];
__device__ float g_P[Bdim][NH][INNER];
__device__ float g_Q[Bdim][NH][INNER];
__device__ float g_vc[Bdim][NH], g_vt[Bdim][NH], g_cov[Bdim][NH];
__device__ float g_PW[Bdim][NH][DIMV];
__device__ float g_QW[Bdim][NH][DIMV];
__device__ float g_GW[DIMV];

// ================= helpers =================
__device__ __forceinline__ uint32_t smem_u32(const void* p) {
    uint32_t a;
    asm("{ .reg .u64 t; cvta.to.shared.u64 t, %1; cvt.u32.u64 %0, t; }" : "=r"(a) : "l"(p));
    return a;
}
#define SWZ64(o) ((o) ^ (((o) >> 3) & 0x30))

__device__ __forceinline__ void cp16(uint32_t saddr, const void* g) {
    asm volatile("cp.async.cg.shared.global [%0], [%1], 16;" :: "r"(saddr), "l"(g));
}
#define CP_COMMIT()  asm volatile("cp.async.commit_group;" ::: "memory")
#define CP_WAIT0()   asm volatile("cp.async.wait_group 0;" ::: "memory")

__device__ __forceinline__ void ldmx4(uint32_t* r, uint32_t addr) {
    asm volatile("ldmatrix.sync.aligned.m8n8.x4.shared.b16 {%0,%1,%2,%3}, [%4];"
        : "=r"(r[0]), "=r"(r[1]), "=r"(r[2]), "=r"(r[3]) : "r"(addr));
}
__device__ __forceinline__ void mma_f16(float* c, const uint32_t* a, const uint32_t* b) {
    asm volatile(
        "mma.sync.aligned.m16n8k16.row.col.f32.f16.f16.f32 "
        "{%0,%1,%2,%3},{%4,%5,%6,%7},{%8,%9},{%0,%1,%2,%3};"
        : "+f"(c[0]), "+f"(c[1]), "+f"(c[2]), "+f"(c[3])
        : "r"(a[0]), "r"(a[1]), "r"(a[2]), "r"(a[3]), "r"(b[0]), "r"(b[1]));
}
__device__ __forceinline__ float siluf(float a) { return a / (1.f + expf(-a)); }

// ================= K0: merged fp32 -> fp16 conversions =================
// regions (float4 units): [0,1M) x -> g_xf ; then Wz, Wza (interleaved into g_wzi), Wya -> g_wy
#define NX4  (MROWS*DIMV/4)     /* 1048576 */
#define NW4  (DIMV*DIMV/4)      /* 262144 */
__global__ void kconv_all(const float* __restrict__ x, const float* __restrict__ Wz,
                          const float* __restrict__ Wza, const float* __restrict__ Wya)
{
    int i = blockIdx.x * blockDim.x + threadIdx.x;
    const float* src;
    __half* dst;
    size_t si, di;
    if (i < NX4) {
        src = x; si = i; dst = g_xf; di = i;
    } else {
        int e = i - NX4;
        int m = e >> 18;                 // 0:Wz 1:Wza 2:Wya
        int e4 = e & (NW4 - 1);
        int row = e4 >> 8, c4 = e4 & 255;
        si = e4;
        if (m == 0)      { src = Wz;  dst = g_wzi; di = (size_t)(2*row)*256 + c4; }
        else if (m == 1) { src = Wza; dst = g_wzi; di = (size_t)(2*row+1)*256 + c4; }
        else             { src = Wya; dst = g_wy;  di = (size_t)row*256 + c4; }
    }
    float4 v = ((const float4*)src)[si];
    __half2 p0 = make_half2(__float2half(v.x), __float2half(v.y));
    __half2 p1 = make_half2(__float2half(v.z), __float2half(v.w));
    uint2 o;
    o.x = *(uint32_t*)&p0;
    o.y = *(uint32_t*)&p1;
    ((uint2*)dst)[di] = o;
}

// ================= GEMM: BM=128, BN=256, BK=32, 512 thr, warp 32x64 =================
// blockIdx.x < 8  : z-branch over g_wzi (2048 interleaved cols), epilogue -> spart/zrows
// blockIdx.x >= 8 : yact-branch over g_wy (1024 cols), epilogue -> g_yact
#define OFF_A  0
#define OFF_B  8192
#define STG    24576
#define RED_OFF (2*STG)
#define GEMM_SMEM (2*STG + 2048)

__global__ void __launch_bounds__(512, 1)
kgemm_h(const float* __restrict__ bz, const float* __restrict__ bza)
{
    extern __shared__ char smem[];
    const uint32_t sb = smem_u32(smem);
    const int tid = threadIdx.x;
    const int wid = tid >> 5, lane = tid & 31;
    const int wm = wid >> 2, wn = wid & 3;          // 4 x 4 warps
    const bool isA = blockIdx.x < 8;
    const int n0 = isA ? blockIdx.x * 256 : (blockIdx.x - 8) * 256;
    const int r0 = blockIdx.y * 128;
    const __half* Bsrc = isA ? g_wzi : g_wy;

    float acc[2][8][4];
#pragma unroll
    for (int m = 0; m < 2; m++)
#pragma unroll
        for (int n = 0; n < 8; n++)
#pragma unroll
            for (int c = 0; c < 4; c++) acc[m][n][c] = 0.f;

    auto load_stage = [&](int stage, int kt) {
        uint32_t base = sb + stage * STG;
        int k0 = kt * 32;
#pragma unroll
        for (int u = 0; u < 3; u++) {
            int i = tid + u * 512;                  // 0..1535
            uint32_t so, dst;
            const __half* src;
            if (i < 512) {
                int row = i >> 2, c = i & 3;
                so  = SWZ64((uint32_t)(row*64 + c*16));
                dst = base + OFF_A + so;
                src = g_xf + (size_t)(r0+row)*DIMV + k0 + c*8;
            } else {
                int idx = i - 512;
                int row = idx >> 2, c = idx & 3;
                so  = SWZ64((uint32_t)(row*64 + c*16));
                dst = base + OFF_B + so;
                src = Bsrc + (size_t)(n0+row)*DIMV + k0 + c*8;
            }
            cp16(dst, src);
        }
    };

    load_stage(0, 0);
    CP_COMMIT();

    for (int it = 0; it < 32; it++) {
        CP_WAIT0();
        __syncthreads();
        if (it + 1 < 32) { load_stage((it+1) & 1, it+1); CP_COMMIT(); }

        uint32_t stg = sb + (it & 1) * STG;
#pragma unroll
        for (int kh = 0; kh < 2; kh++) {
            uint32_t af[2][4];
#pragma unroll
            for (int m = 0; m < 2; m++) {
                int row = wm*32 + m*16 + (lane & 15);
                uint32_t so = SWZ64((uint32_t)(row*64 + (kh*2 + (lane >> 4))*16));
                ldmx4(af[m], stg + OFF_A + so);
            }
#pragma unroll
            for (int p = 0; p < 4; p++) {
                int row = wn*64 + p*16 + (lane & 7) + ((lane >> 4) & 1) * 8;
                uint32_t so = SWZ64((uint32_t)(row*64 + (kh*2 + ((lane >> 3) & 1))*16));
                uint32_t bt[4];
                ldmx4(bt, stg + OFF_B + so);
#pragma unroll
                for (int m = 0; m < 2; m++) {
                    mma_f16(acc[m][2*p],   af[m], &bt[0]);
                    mma_f16(acc[m][2*p+1], af[m], &bt[2]);
                }
            }
        }
        __syncthreads();
    }

    if (!isA) {
        // ---- yact epilogue ----
#pragma unroll
        for (int m = 0; m < 2; m++) {
            int rowA = r0 + wm*32 + m*16 + (lane >> 2);
#pragma unroll
            for (int n = 0; n < 8; n++) {
                int col = n0 + wn*64 + n*8 + (lane & 3)*2;
                *(float2*)(g_yact + (size_t)rowA*DIMV + col)     = make_float2(acc[m][n][0], acc[m][n][1]);
                *(float2*)(g_yact + (size_t)(rowA+8)*DIMV + col) = make_float2(acc[m][n][2], acc[m][n][3]);
            }
        }
        return;
    }

    // ---- z epilogue: z = (lin+bz)*silu(act+bza); masked colsums; zrows ----
    float* red = (float*)(smem + RED_OFF);          // [4][128]
    const int g = lane >> 2, q = lane & 3;
    const int bI = r0 >> 11;
    float zsum[8];
#pragma unroll
    for (int n = 0; n < 8; n++) {
        int jz = (n0 >> 1) + wn*32 + n*4 + q;       // z column 0..1023
        int h  = jz >> 7;
        float bzv = bz[jz], bzav = bza[jz];
        float s = 0.f;
#pragma unroll
        for (int m = 0; m < 2; m++) {
            int rowb = wm*32 + m*16 + g;
            float z0 = (acc[m][n][0] + bzv) * siluf(acc[m][n][1] + bzav);
            float z1 = (acc[m][n][2] + bzv) * siluf(acc[m][n][3] + bzav);
            int l0 = (r0 + rowb) & (Ldim-1);
            int l1 = (r0 + rowb + 8) & (Ldim-1);
            if (l0 > h) s += z0;
            if (l1 > h) s += z1;
            if (m == 0 && wm == 0 && ((r0 & (Ldim-1)) == 0))
                g_zrows[bI][g][jz] = z0;            // rows l=0..7
        }
        zsum[n] = s;
    }
    // reduce over row groups g (lanes 4,8,16 apart)
#pragma unroll
    for (int n = 0; n < 8; n++) {
        for (int off = 4; off < 32; off <<= 1)
            zsum[n] += __shfl_xor_sync(0xffffffffu, zsum[n], off);
    }
    if (g == 0) {
#pragma unroll
        for (int n = 0; n < 8; n++)
            red[wm*128 + wn*32 + n*4 + q] = zsum[n];
    }
    __syncthreads();
    if (tid < 128) {
        float s = red[tid] + red[128 + tid] + red[256 + tid] + red[384 + tid];
        g_spart[r0 >> 7][(n0 >> 1) + tid] = s;
    }
}

// ================= K1a: dt projection (warp per row) =================
__global__ void k1_dt(const float* __restrict__ x, const float* __restrict__ Wdt,
                      const float* __restrict__ bdt, const float* __restrict__ lna)
{
    int gw   = (blockIdx.x * blockDim.x + threadIdx.x) >> 5;
    int lane = threadIdx.x & 31;
    if (gw >= MROWS) return;
    const float* xr = x + (size_t)gw * DIMV;
    float acc[NH];
#pragma unroll
    for (int h = 0; h < NH; h++) acc[h] = 0.f;
    for (int k = lane; k < DIMV; k += 32) {
        float xv = xr[k];
#pragma unroll
        for (int h = 0; h < NH; h++) acc[h] += xv * Wdt[h*DIMV + k];
    }
#pragma unroll
    for (int h = 0; h < NH; h++)
        for (int off = 16; off; off >>= 1)
            acc[h] += __shfl_xor_sync(0xffffffffu, acc[h], off);
    if (lane == 0) {
        int b = gw >> 11, l = gw & (Ldim-1);
#pragma unroll
        for (int h = 0; h < NH; h++) {
            float v  = acc[h] + bdt[h];
            float sp = fmaxf(v, 0.f) + log1pf(expf(-fabsf(v)));
            g_lda[b][h][l] = -expf(lna[h]) * sp;
        }
    }
}

// ================= K1b: inclusive scan + exp =================
__global__ void k1b_scan()
{
    int b = blockIdx.x >> 3, h = blockIdx.x & 7;
    int t = threadIdx.x;
    const float* src = g_lda[b][h];
    int base = t * 8;
    float v[8]; float s = 0.f;
#pragma unroll
    for (int u = 0; u < 8; u++) { v[u] = src[base+u]; s += v[u]; }
    __shared__ float sm[256];
    sm[t] = s; __syncthreads();
    for (int d = 1; d < 256; d <<= 1) {
        float add = (t >= d) ? sm[t-d] : 0.f;
        __syncthreads();
        sm[t] += add;
        __syncthreads();
    }
    float run = sm[t] - s;
#pragma unroll
    for (int u = 0; u < 8; u++) { run += v[u]; g_Acum[b][h][base+u] = expf(run); }
}

// ================= K3: per-(b,h) stats =================
__device__ __forceinline__ float blockSum128(float v, float* sm)
{
    for (int off = 16; off; off >>= 1) v += __shfl_xor_sync(0xffffffffu, v, off);
    int w = threadIdx.x >> 5;
    if ((threadIdx.x & 31) == 0) sm[w] = v;
    __syncthreads();
    float r = sm[0] + sm[1] + sm[2] + sm[3];
    __syncthreads();
    return r;
}

__global__ void k3_stats(const float* __restrict__ hidden, const float* __restrict__ gnw,
                         float* __restrict__ out, int writeHidden)
{
    int b = blockIdx.x >> 3, h = blockIdx.x & 7;
    int i = threadIdx.x;
    int col = h*INNER + i;
    float S = 0.f;
#pragma unroll 8
    for (int t = 0; t < MROWS/128/Bdim; t++)    // 16 tiles per batch
        S += g_spart[b*(MROWS/128/Bdim) + t][col];
    float c  = g_zrows[b][h][col];
    float tv = S + hidden[(b*NH+h)*INNER + i];

    __shared__ float sm[4];
    float mc = blockSum128(c,  sm) * (1.f/INNER);
    float mt = blockSum128(tv, sm) * (1.f/INNER);
    float dc = c - mc, dq = tv - mt;
    float vc = blockSum128(dc*dc, sm) * (1.f/INNER);
    float vt = blockSum128(dq*dq, sm) * (1.f/INNER);
    float cv = blockSum128(dc*dq, sm) * (1.f/INNER);
    if (i == 0) { g_vc[b][h]=vc; g_vt[b][h]=vt; g_cov[b][h]=cv; }
    float w = gnw[h];
    g_P[b][h][i] = dc * w;
    g_Q[b][h][i] = dq * w;
    if (writeHidden)
        out[(size_t)MROWS*DIMV + (b*NH+h)*INNER + i] = c + g_Acum[b][h][Ldim-1]*tv;
}

// ================= K4: rank-16 projections through W_y =================
__global__ void k4_proj(const float* __restrict__ Wy, const float* __restrict__ by,
                        const float* __restrict__ gnb)
{
    __shared__ float Ps[Bdim*NH*INNER];
    __shared__ float Qs[Bdim*NH*INNER];
    for (int idx = threadIdx.x; idx < Bdim*NH*INNER; idx += blockDim.x) {
        Ps[idx] = ((const float*)g_P)[idx];
        Qs[idx] = ((const float*)g_Q)[idx];
    }
    __syncthreads();
    int j    = (blockIdx.x * blockDim.x + threadIdx.x) >> 5;
    int lane = threadIdx.x & 31;
    if (j >= DIMV) return;
    const float* wrow = Wy + (size_t)j*DIMV;
    float gb = 0.f;
#pragma unroll
    for (int h = 0; h < NH; h++) {
        float aP0=0.f, aQ0=0.f, aP1=0.f, aQ1=0.f, aW=0.f;
#pragma unroll
        for (int kk = 0; kk < 4; kk++) {
            int ii = kk*32 + lane;
            float w = wrow[h*INNER + ii];
            aW  += w;
            aP0 += w * Ps[(0*NH+h)*INNER + ii];
            aQ0 += w * Qs[(0*NH+h)*INNER + ii];
            aP1 += w * Ps[(1*NH+h)*INNER + ii];
            aQ1 += w * Qs[(1*NH+h)*INNER + ii];
        }
        for (int off = 16; off; off >>= 1) {
            aP0 += __shfl_xor_sync(0xffffffffu, aP0, off);
            aQ0 += __shfl_xor_sync(0xffffffffu, aQ0, off);
            aP1 += __shfl_xor_sync(0xffffffffu, aP1, off);
            aQ1 += __shfl_xor_sync(0xffffffffu, aQ1, off);
            aW  += __shfl_xor_sync(0xffffffffu, aW,  off);
        }
        if (lane == 0) {
            g_PW[0][h][j] = aP0;  g_QW[0][h][j] = aQ0;
            g_PW[1][h][j] = aP1;  g_QW[1][h][j] = aQ1;
            gb += gnb[h] * aW;
        }
    }
    if (lane == 0) g_GW[j] = by[j] + gb;
}

// ================= K5: final combine =================
__global__ void k5_final(float* __restrict__ out, const float* __restrict__ bya)
{
    int r = blockIdx.x;
    int b = r >> 11, l = r & (Ldim-1);
    __shared__ float cP[NH], cQ[NH];
    if (threadIdx.x < NH) {
        int h = threadIdx.x;
        float A   = g_Acum[b][h][l];
        float var = g_vc[b][h] + 2.f*A*g_cov[b][h] + A*A*g_vt[b][h];
        float inv = rsqrtf(var + EPSV);
        cP[h] = inv;
        cQ[h] = A * inv;
    }
    __syncthreads();
    for (int j = threadIdx.x; j < DIMV; j += blockDim.x) {
        float y0 = g_GW[j];
#pragma unroll
        for (int h = 0; h < NH; h++)
            y0 += cP[h]*g_PW[b][h][j] + cQ[h]*g_QW[b][h][j];
        float ya = g_yact[(size_t)r*DIMV + j] + bya[j];
        out[(size_t)r*DIMV + j] = y0 * siluf(ya);
    }
}

// ================= launch =================
extern "C" void kernel_launch(void* const* d_in, const int* in_sizes, int n_in,
                              void* d_out, int out_size)
{
    const float* x    = (const float*)d_in[0];
    const float* hid  = (const float*)d_in[1];
    const float* W_z  = (const float*)d_in[2];
    const float* b_z  = (const float*)d_in[3];
    const float* W_za = (const float*)d_in[4];
    const float* b_za = (const float*)d_in[5];
    const float* W_y  = (const float*)d_in[6];
    const float* b_y  = (const float*)d_in[7];
    const float* W_ya = (const float*)d_in[8];
    const float* b_ya = (const float*)d_in[9];
    const float* W_dt = (const float*)d_in[10];
    const float* b_dt = (const float*)d_in[11];
    const float* ln_a = (const float*)d_in[12];
    const float* gn_w = (const float*)d_in[13];
    const float* gn_b = (const float*)d_in[14];
    float* out = (float*)d_out;
    int writeHidden = (out_size >= MROWS*DIMV + Bdim*NH*INNER) ? 1 : 0;

    cudaFuncSetAttribute(kgemm_h, cudaFuncAttributeMaxDynamicSharedMemorySize, GEMM_SMEM);

    const int NTOT = NX4 + 3*NW4;               // 1835008
    kconv_all<<<NTOT/256, 256>>>(x, W_z, W_za, W_ya);

    k1_dt<<<MROWS/8, 256>>>(x, W_dt, b_dt, ln_a);

    dim3 gg(12, MROWS/128);                     // x: 8 z-blocks + 4 yact-blocks
    kgemm_h<<<gg, 512, GEMM_SMEM>>>(b_z, b_za);

    k1b_scan<<<Bdim*NH, 256>>>();
    k3_stats<<<Bdim*NH, INNER>>>(hid, gn_w, out, writeHidden);
    k4_proj<<<DIMV/8, 256>>>(W_y, b_y, gn_b);
    k5_final<<<MROWS, 256>>>(out, b_ya);
}

// round 16
// speedup vs baseline: 5.1801x; 1.0167x over previous
#include <cuda_runtime.h>
#include <cuda_fp16.h>
#include <cstdint>
#include <math.h>

#define Bdim   2
#define Ldim   2048
#define DIMV   1024
#define NH     8
#define INNER  128
#define MROWS  (Bdim*Ldim)   /* 4096 */
#define EPSV   1e-5f

// ---------------- scratch (static __device__, no allocs) ----------------
// g_xf : tiled [r0_tile(32)][kt(32)][128 rows][64B], SWZ64-preswizzled per tile
// g_wzi: tiled [n0_tile(8) ][kt(32)][256 rows][64B], rows interleaved 2j=Wz[j], 2j+1=Wza[j]
// g_wy : tiled [n0_tile(4) ][kt(32)][256 rows][64B]
__device__ __half g_xf[(size_t)MROWS*DIMV];
__device__ __half g_wzi[(size_t)2048*DIMV];
__device__ __half g_wy[(size_t)DIMV*DIMV];
__device__ float g_yact[(size_t)MROWS*DIMV];        // x @ Wya^T (16MB)
__device__ float g_spart[MROWS/128][DIMV];          // per-128-row-tile masked colsums of z
__device__ float g_zrows[Bdim][NH][DIMV];
__device__ float g_lda [Bdim][NH][Ldim];
__device__ float g_Acum[Bdim][NH][Ldim];
__device__ float g_P[Bdim][NH][INNER];
__device__ float g_Q[Bdim][NH][INNER];
__device__ float g_vc[Bdim][NH], g_vt[Bdim][NH], g_cov[Bdim][NH];
__device__ float g_PW[Bdim][NH][DIMV];
__device__ float g_QW[Bdim][NH][DIMV];
__device__ float g_GW[DIMV];

// ================= helpers =================
__device__ __forceinline__ uint32_t smem_u32(const void* p) {
    uint32_t a;
    asm("{ .reg .u64 t; cvta.to.shared.u64 t, %1; cvt.u32.u64 %0, t; }" : "=r"(a) : "l"(p));
    return a;
}
#define SWZ64(o) ((o) ^ (((o) >> 3) & 0x30))

__device__ __forceinline__ void ldmx4(uint32_t* r, uint32_t addr) {
    asm volatile("ldmatrix.sync.aligned.m8n8.x4.shared.b16 {%0,%1,%2,%3}, [%4];"
        : "=r"(r[0]), "=r"(r[1]), "=r"(r[2]), "=r"(r[3]) : "r"(addr));
}
__device__ __forceinline__ void mma_f16(float* c, const uint32_t* a, const uint32_t* b) {
    asm volatile(
        "mma.sync.aligned.m16n8k16.row.col.f32.f16.f16.f32 "
        "{%0,%1,%2,%3},{%4,%5,%6,%7},{%8,%9},{%0,%1,%2,%3};"
        : "+f"(c[0]), "+f"(c[1]), "+f"(c[2]), "+f"(c[3])
        : "r"(a[0]), "r"(a[1]), "r"(a[2]), "r"(a[3]), "r"(b[0]), "r"(b[1]));
}
__device__ __forceinline__ float siluf(float a) { return a / (1.f + expf(-a)); }

// ---- 1D bulk copy (sm_90+, not arch-suffixed) + mbarrier ----
__device__ __forceinline__ void bulkcp(uint32_t dst, const void* src, uint32_t bytes, uint32_t mbar) {
    asm volatile("cp.async.bulk.shared::cluster.global.mbarrier::complete_tx::bytes [%0], [%1], %2, [%3];"
        :: "r"(dst), "l"(src), "r"(bytes), "r"(mbar) : "memory");
}
#define MBAR_INIT(mb, c)  asm volatile("mbarrier.init.shared.b64 [%0], %1;" :: "r"(mb), "r"(c) : "memory")
#define MBAR_EXPECT(mb, n) asm volatile("mbarrier.arrive.expect_tx.shared.b64 _, [%0], %1;" :: "r"(mb), "r"(n) : "memory")
#define MBAR_WAIT(mb, ph) do { \
    uint32_t _m = (mb), _p = (ph), _d; \
    asm volatile("{ .reg .pred p; mbarrier.try_wait.parity.acquire.cta.shared::cta.b64 p, [%1], %2; selp.b32 %0,1,0,p; }" \
        : "=r"(_d) : "r"(_m), "r"(_p) : "memory"); \
    if (!_d) { \
        asm volatile("{ .reg .pred P1;\nWL_%=:\n mbarrier.try_wait.parity.acquire.cta.shared::cta.b64 P1, [%0], %1, 0x989680;\n @P1 bra.uni WD_%=;\n bra.uni WL_%=;\nWD_%=:\n}" \
            :: "r"(_m), "r"(_p) : "memory"); \
    } } while (0)

// ================= K0: fp32 -> fp16 into tiled, pre-swizzled layout =================
// one thread = one 16B fp16 chunk (8 elems)
#define NX8  (MROWS*DIMV/8)     /* 524288 */
#define NW8  (DIMV*DIMV/8)      /* 131072 */
__global__ void kconv_all(const float* __restrict__ x, const float* __restrict__ Wz,
                          const float* __restrict__ Wza, const float* __restrict__ Wya)
{
    int i = blockIdx.x * blockDim.x + threadIdx.x;
    const float* src;
    __half* base;
    size_t soff, doff;
    if (i < NX8) {
        int r = i >> 7, c = i & 127;
        int kt = c >> 2, cc = c & 3;
        int T = (r >> 7)*32 + kt;
        src = x; soff = (size_t)r*DIMV + c*8;
        base = g_xf;
        doff = (size_t)T*8192 + SWZ64((uint32_t)(((r & 127) << 6) | (cc << 4)));
    } else {
        int e = i - NX8;
        int m = e >> 17;                 // 0:Wz 1:Wza 2:Wya
        e &= (NW8 - 1);
        int j = e >> 7, c = e & 127;
        int kt = c >> 2, cc = c & 3;
        int n;
        if (m == 0)      { src = Wz;  base = g_wzi; n = 2*j; }
        else if (m == 1) { src = Wza; base = g_wzi; n = 2*j + 1; }
        else             { src = Wya; base = g_wy;  n = j; }
        int T = (n >> 8)*32 + kt;
        soff = (size_t)j*DIMV + c*8;
        doff = (size_t)T*16384 + SWZ64((uint32_t)(((n & 255) << 6) | (cc << 4)));
    }
    float4 v0 = ((const float4*)(src + soff))[0];
    float4 v1 = ((const float4*)(src + soff))[1];
    __half2 h0 = make_half2(__float2half(v0.x), __float2half(v0.y));
    __half2 h1 = make_half2(__float2half(v0.z), __float2half(v0.w));
    __half2 h2 = make_half2(__float2half(v1.x), __float2half(v1.y));
    __half2 h3 = make_half2(__float2half(v1.z), __float2half(v1.w));
    uint4 o;
    o.x = *(uint32_t*)&h0; o.y = *(uint32_t*)&h1;
    o.z = *(uint32_t*)&h2; o.w = *(uint32_t*)&h3;
    *(uint4*)((char*)base + doff) = o;
}

// ================= GEMM: BM=128, BN=256, BK=32, 512 thr, warp 32x64 =================
// per stage: ONE 8KB bulk (A) + ONE 16KB bulk (B), mbarrier-paced double buffer
#define OFF_A  0
#define OFF_B  8192
#define STG    24576
#define RED_OFF  (2*STG)            /* 2048B reduction scratch */
#define MBAR_OFF (2*STG + 2048)
#define GEMM_SMEM (2*STG + 2048 + 16)

__global__ void __launch_bounds__(512, 1)
kgemm_h(const float* __restrict__ bz, const float* __restrict__ bza)
{
    extern __shared__ char smem[];
    const uint32_t sb = smem_u32(smem);
    const uint32_t mb = sb + MBAR_OFF;
    const int tid = threadIdx.x;
    const int wid = tid >> 5, lane = tid & 31;
    const int wm = wid >> 2, wn = wid & 3;          // 4 x 4 warps
    const bool isA = blockIdx.x < 8;
    const int tI = isA ? blockIdx.x : (blockIdx.x - 8);
    const int n0 = tI * 256;
    const int r0 = blockIdx.y * 128;
    const char* Abase = (const char*)g_xf + (size_t)blockIdx.y * 32 * 8192;
    const char* Bbase = (isA ? (const char*)g_wzi : (const char*)g_wy) + (size_t)tI * 32 * 16384;

    float acc[2][8][4];
#pragma unroll
    for (int m = 0; m < 2; m++)
#pragma unroll
        for (int n = 0; n < 8; n++)
#pragma unroll
            for (int c = 0; c < 4; c++) acc[m][n][c] = 0.f;

    if (tid == 0) { MBAR_INIT(mb, 1); MBAR_INIT(mb + 8, 1); }
    __syncthreads();

    if (tid == 0) {
        MBAR_EXPECT(mb, 24576u);
        bulkcp(sb + OFF_A, Abase, 8192u, mb);
        bulkcp(sb + OFF_B, Bbase, 16384u, mb);
    }

    for (int it = 0; it < 32; it++) {
        if (tid == 0 && it + 1 < 32) {
            int s = (it + 1) & 1;
            uint32_t m2 = mb + 8*s;
            MBAR_EXPECT(m2, 24576u);
            bulkcp(sb + s*STG + OFF_A, Abase + (size_t)(it+1)*8192,  8192u,  m2);
            bulkcp(sb + s*STG + OFF_B, Bbase + (size_t)(it+1)*16384, 16384u, m2);
        }
        MBAR_WAIT(mb + 8*(it & 1), (uint32_t)((it >> 1) & 1));

        uint32_t stg = sb + (it & 1) * STG;
#pragma unroll
        for (int kh = 0; kh < 2; kh++) {
            uint32_t af[2][4];
#pragma unroll
            for (int m = 0; m < 2; m++) {
                int row = wm*32 + m*16 + (lane & 15);
                uint32_t so = SWZ64((uint32_t)(row*64 + (kh*2 + (lane >> 4))*16));
                ldmx4(af[m], stg + OFF_A + so);
            }
#pragma unroll
            for (int p = 0; p < 4; p++) {
                int row = wn*64 + p*16 + (lane & 7) + ((lane >> 4) & 1) * 8;
                uint32_t so = SWZ64((uint32_t)(row*64 + (kh*2 + ((lane >> 3) & 1))*16));
                uint32_t bt[4];
                ldmx4(bt, stg + OFF_B + so);
#pragma unroll
                for (int m = 0; m < 2; m++) {
                    mma_f16(acc[m][2*p],   af[m], &bt[0]);
                    mma_f16(acc[m][2*p+1], af[m], &bt[2]);
                }
            }
        }
        __syncthreads();
    }

    if (!isA) {
        // ---- yact epilogue ----
#pragma unroll
        for (int m = 0; m < 2; m++) {
            int rowA = r0 + wm*32 + m*16 + (lane >> 2);
#pragma unroll
            for (int n = 0; n < 8; n++) {
                int col = n0 + wn*64 + n*8 + (lane & 3)*2;
                *(float2*)(g_yact + (size_t)rowA*DIMV + col)     = make_float2(acc[m][n][0], acc[m][n][1]);
                *(float2*)(g_yact + (size_t)(rowA+8)*DIMV + col) = make_float2(acc[m][n][2], acc[m][n][3]);
            }
        }
        return;
    }

    // ---- z epilogue: z = (lin+bz)*silu(act+bza); masked colsums; zrows ----
    float* red = (float*)(smem + RED_OFF);          // [4][128]
    const int g = lane >> 2, q = lane & 3;
    const int bI = r0 >> 11;
    float zsum[8];
#pragma unroll
    for (int n = 0; n < 8; n++) {
        int jz = (n0 >> 1) + wn*32 + n*4 + q;       // z column 0..1023
        int h  = jz >> 7;
        float bzv = bz[jz], bzav = bza[jz];
        float s = 0.f;
#pragma unroll
        for (int m = 0; m < 2; m++) {
            int rowb = wm*32 + m*16 + g;
            float z0 = (acc[m][n][0] + bzv) * siluf(acc[m][n][1] + bzav);
            float z1 = (acc[m][n][2] + bzv) * siluf(acc[m][n][3] + bzav);
            int l0 = (r0 + rowb) & (Ldim-1);
            int l1 = (r0 + rowb + 8) & (Ldim-1);
            if (l0 > h) s += z0;
            if (l1 > h) s += z1;
            if (m == 0 && wm == 0 && ((r0 & (Ldim-1)) == 0))
                g_zrows[bI][g][jz] = z0;            // rows l=0..7
        }
        zsum[n] = s;
    }
#pragma unroll
    for (int n = 0; n < 8; n++) {
        for (int off = 4; off < 32; off <<= 1)
            zsum[n] += __shfl_xor_sync(0xffffffffu, zsum[n], off);
    }
    if (g == 0) {
#pragma unroll
        for (int n = 0; n < 8; n++)
            red[wm*128 + wn*32 + n*4 + q] = zsum[n];
    }
    __syncthreads();
    if (tid < 128) {
        float s = red[tid] + red[128 + tid] + red[256 + tid] + red[384 + tid];
        g_spart[r0 >> 7][(n0 >> 1) + tid] = s;
    }
}

// ================= K1a: dt projection (warp per row) =================
__global__ void k1_dt(const float* __restrict__ x, const float* __restrict__ Wdt,
                      const float* __restrict__ bdt, const float* __restrict__ lna)
{
    int gw   = (blockIdx.x * blockDim.x + threadIdx.x) >> 5;
    int lane = threadIdx.x & 31;
    if (gw >= MROWS) return;
    const float* xr = x + (size_t)gw * DIMV;
    float acc[NH];
#pragma unroll
    for (int h = 0; h < NH; h++) acc[h] = 0.f;
    for (int k = lane; k < DIMV; k += 32) {
        float xv = xr[k];
#pragma unroll
        for (int h = 0; h < NH; h++) acc[h] += xv * Wdt[h*DIMV + k];
    }
#pragma unroll
    for (int h = 0; h < NH; h++)
        for (int off = 16; off; off >>= 1)
            acc[h] += __shfl_xor_sync(0xffffffffu, acc[h], off);
    if (lane == 0) {
        int b = gw >> 11, l = gw & (Ldim-1);
#pragma unroll
        for (int h = 0; h < NH; h++) {
            float v  = acc[h] + bdt[h];
            float sp = fmaxf(v, 0.f) + log1pf(expf(-fabsf(v)));
            g_lda[b][h][l] = -expf(lna[h]) * sp;
        }
    }
}

// ================= K1b: inclusive scan + exp =================
__global__ void k1b_scan()
{
    int b = blockIdx.x >> 3, h = blockIdx.x & 7;
    int t = threadIdx.x;
    const float* src = g_lda[b][h];
    int base = t * 8;
    float v[8]; float s = 0.f;
#pragma unroll
    for (int u = 0; u < 8; u++) { v[u] = src[base+u]; s += v[u]; }
    __shared__ float sm[256];
    sm[t] = s; __syncthreads();
    for (int d = 1; d < 256; d <<= 1) {
        float add = (t >= d) ? sm[t-d] : 0.f;
        __syncthreads();
        sm[t] += add;
        __syncthreads();
    }
    float run = sm[t] - s;
#pragma unroll
    for (int u = 0; u < 8; u++) { run += v[u]; g_Acum[b][h][base+u] = expf(run); }
}

// ================= K3: per-(b,h) stats =================
__device__ __forceinline__ float blockSum128(float v, float* sm)
{
    for (int off = 16; off; off >>= 1) v += __shfl_xor_sync(0xffffffffu, v, off);
    int w = threadIdx.x >> 5;
    if ((threadIdx.x & 31) == 0) sm[w] = v;
    __syncthreads();
    float r = sm[0] + sm[1] + sm[2] + sm[3];
    __syncthreads();
    return r;
}

__global__ void k3_stats(const float* __restrict__ hidden, const float* __restrict__ gnw,
                         float* __restrict__ out, int writeHidden)
{
    int b = blockIdx.x >> 3, h = blockIdx.x & 7;
    int i = threadIdx.x;
    int col = h*INNER + i;
    float S = 0.f;
#pragma unroll 8
    for (int t = 0; t < MROWS/128/Bdim; t++)    // 16 tiles per batch
        S += g_spart[b*(MROWS/128/Bdim) + t][col];
    float c  = g_zrows[b][h][col];
    float tv = S + hidden[(b*NH+h)*INNER + i];

    __shared__ float sm[4];
    float mc = blockSum128(c,  sm) * (1.f/INNER);
    float mt = blockSum128(tv, sm) * (1.f/INNER);
    float dc = c - mc, dq = tv - mt;
    float vc = blockSum128(dc*dc, sm) * (1.f/INNER);
    float vt = blockSum128(dq*dq, sm) * (1.f/INNER);
    float cv = blockSum128(dc*dq, sm) * (1.f/INNER);
    if (i == 0) { g_vc[b][h]=vc; g_vt[b][h]=vt; g_cov[b][h]=cv; }
    float w = gnw[h];
    g_P[b][h][i] = dc * w;
    g_Q[b][h][i] = dq * w;
    if (writeHidden)
        out[(size_t)MROWS*DIMV + (b*NH+h)*INNER + i] = c + g_Acum[b][h][Ldim-1]*tv;
}

// ================= K4: rank-16 projections through W_y =================
__global__ void k4_proj(const float* __restrict__ Wy, const float* __restrict__ by,
                        const float* __restrict__ gnb)
{
    __shared__ float Ps[Bdim*NH*INNER];
    __shared__ float Qs[Bdim*NH*INNER];
    for (int idx = threadIdx.x; idx < Bdim*NH*INNER; idx += blockDim.x) {
        Ps[idx] = ((const float*)g_P)[idx];
        Qs[idx] = ((const float*)g_Q)[idx];
    }
    __syncthreads();
    int j    = (blockIdx.x * blockDim.x + threadIdx.x) >> 5;
    int lane = threadIdx.x & 31;
    if (j >= DIMV) return;
    const float* wrow = Wy + (size_t)j*DIMV;
    float gb = 0.f;
#pragma unroll
    for (int h = 0; h < NH; h++) {
        float aP0=0.f, aQ0=0.f, aP1=0.f, aQ1=0.f, aW=0.f;
#pragma unroll
        for (int kk = 0; kk < 4; kk++) {
            int ii = kk*32 + lane;
            float w = wrow[h*INNER + ii];
            aW  += w;
            aP0 += w * Ps[(0*NH+h)*INNER + ii];
            aQ0 += w * Qs[(0*NH+h)*INNER + ii];
            aP1 += w * Ps[(1*NH+h)*INNER + ii];
            aQ1 += w * Qs[(1*NH+h)*INNER + ii];
        }
        for (int off = 16; off; off >>= 1) {
            aP0 += __shfl_xor_sync(0xffffffffu, aP0, off);
            aQ0 += __shfl_xor_sync(0xffffffffu, aQ0, off);
            aP1 += __shfl_xor_sync(0xffffffffu, aP1, off);
            aQ1 += __shfl_xor_sync(0xffffffffu, aQ1, off);
            aW  += __shfl_xor_sync(0xffffffffu, aW,  off);
        }
        if (lane == 0) {
            g_PW[0][h][j] = aP0;  g_QW[0][h][j] = aQ0;
            g_PW[1][h][j] = aP1;  g_QW[1][h][j] = aQ1;
            gb += gnb[h] * aW;
        }
    }
    if (lane == 0) g_GW[j] = by[j] + gb;
}

// ================= K5: final combine =================
__global__ void k5_final(float* __restrict__ out, const float* __restrict__ bya)
{
    int r = blockIdx.x;
    int b = r >> 11, l = r & (Ldim-1);
    __shared__ float cP[NH], cQ[NH];
    if (threadIdx.x < NH) {
        int h = threadIdx.x;
        float A   = g_Acum[b][h][l];
        float var = g_vc[b][h] + 2.f*A*g_cov[b][h] + A*A*g_vt[b][h];
        float inv = rsqrtf(var + EPSV);
        cP[h] = inv;
        cQ[h] = A * inv;
    }
    __syncthreads();
    for (int j = threadIdx.x; j < DIMV; j += blockDim.x) {
        float y0 = g_GW[j];
#pragma unroll
        for (int h = 0; h < NH; h++)
            y0 += cP[h]*g_PW[b][h][j] + cQ[h]*g_QW[b][h][j];
        float ya = g_yact[(size_t)r*DIMV + j] + bya[j];
        out[(size_t)r*DIMV + j] = y0 * siluf(ya);
    }
}

// ================= launch =================
extern "C" void kernel_launch(void* const* d_in, const int* in_sizes, int n_in,
                              void* d_out, int out_size)
{
    const float* x    = (const float*)d_in[0];
    const float* hid  = (const float*)d_in[1];
    const float* W_z  = (const float*)d_in[2];
    const float* b_z  = (const float*)d_in[3];
    const float* W_za = (const float*)d_in[4];
    const float* b_za = (const float*)d_in[5];
    const float* W_y  = (const float*)d_in[6];
    const float* b_y  = (const float*)d_in[7];
    const float* W_ya = (const float*)d_in[8];
    const float* b_ya = (const float*)d_in[9];
    const float* W_dt = (const float*)d_in[10];
    const float* b_dt = (const float*)d_in[11];
    const float* ln_a = (const float*)d_in[12];
    const float* gn_w = (const float*)d_in[13];
    const float* gn_b = (const float*)d_in[14];
    float* out = (float*)d_out;
    int writeHidden = (out_size >= MROWS*DIMV + Bdim*NH*INNER) ? 1 : 0;

    cudaFuncSetAttribute(kgemm_h, cudaFuncAttributeMaxDynamicSharedMemorySize, GEMM_SMEM);

    const int NTOT = NX8 + 3*NW8;               // 917504
    kconv_all<<<NTOT/256, 256>>>(x, W_z, W_za, W_ya);

    k1_dt<<<MROWS/8, 256>>>(x, W_dt, b_dt, ln_a);

    dim3 gg(12, MROWS/128);                     // x: 8 z-blocks + 4 yact-blocks
    kgemm_h<<<gg, 512, GEMM_SMEM>>>(b_z, b_za);

    k1b_scan<<<Bdim*NH, 256>>>();
    k3_stats<<<Bdim*NH, INNER>>>(hid, gn_w, out, writeHidden);
    k4_proj<<<DIMV/8, 256>>>(W_y, b_y, gn_b);
    k5_final<<<MROWS, 256>>>(out, b_ya);
}

// round 17
// speedup vs baseline: 6.1015x; 1.1779x over previous
#include <cuda_runtime.h>
#include <cuda_fp16.h>
#include <cstdint>
#include <math.h>

#define Bdim   2
#define Ldim   2048
#define DIMV   1024
#define NH     8
#define INNER  128
#define MROWS  (Bdim*Ldim)   /* 4096 */
#define EPSV   1e-5f

// ---------------- scratch (static __device__, no allocs) ----------------
// g_xf : tiled [r_tile(32)][kt(32)][128 rows][64B], SWZ64-preswizzled (8KB tiles)
// g_wzi: tiled [n_tile(16)][kt(32)][128 rows][64B], rows interleaved 2j=Wz[j], 2j+1=Wza[j]
// g_wy : tiled [n_tile(8) ][kt(32)][128 rows][64B]
__device__ __half g_xf[(size_t)MROWS*DIMV];
__device__ __half g_wzi[(size_t)2048*DIMV];
__device__ __half g_wy[(size_t)DIMV*DIMV];
__device__ float g_yact[(size_t)MROWS*DIMV];        // x @ Wya^T (16MB)
__device__ float g_spart[MROWS/128][DIMV];          // per-128-row-tile masked colsums of z
__device__ float g_zrows[Bdim][NH][DIMV];
__device__ float g_lda [Bdim][NH][Ldim];
__device__ float g_Acum[Bdim][NH][Ldim];
__device__ float g_P[Bdim][NH][INNER];
__device__ float g_Q[Bdim][NH][INNER];
__device__ float g_vc[Bdim][NH], g_vt[Bdim][NH], g_cov[Bdim][NH];
__device__ float g_PW[Bdim][NH][DIMV];
__device__ float g_QW[Bdim][NH][DIMV];
__device__ float g_GW[DIMV];

// ================= helpers =================
__device__ __forceinline__ uint32_t smem_u32(const void* p) {
    uint32_t a;
    asm("{ .reg .u64 t; cvta.to.shared.u64 t, %1; cvt.u32.u64 %0, t; }" : "=r"(a) : "l"(p));
    return a;
}
#define SWZ64(o) ((o) ^ (((o) >> 3) & 0x30))

__device__ __forceinline__ void ldmx4(uint32_t* r, uint32_t addr) {
    asm volatile("ldmatrix.sync.aligned.m8n8.x4.shared.b16 {%0,%1,%2,%3}, [%4];"
        : "=r"(r[0]), "=r"(r[1]), "=r"(r[2]), "=r"(r[3]) : "r"(addr));
}
__device__ __forceinline__ void mma_f16(float* c, const uint32_t* a, const uint32_t* b) {
    asm volatile(
        "mma.sync.aligned.m16n8k16.row.col.f32.f16.f16.f32 "
        "{%0,%1,%2,%3},{%4,%5,%6,%7},{%8,%9},{%0,%1,%2,%3};"
        : "+f"(c[0]), "+f"(c[1]), "+f"(c[2]), "+f"(c[3])
        : "r"(a[0]), "r"(a[1]), "r"(a[2]), "r"(a[3]), "r"(b[0]), "r"(b[1]));
}
__device__ __forceinline__ float siluf(float a) { return a / (1.f + expf(-a)); }

// ---- 1D bulk copy (sm_90+, not arch-suffixed) + mbarrier ----
__device__ __forceinline__ void bulkcp(uint32_t dst, const void* src, uint32_t bytes, uint32_t mbar) {
    asm volatile("cp.async.bulk.shared::cluster.global.mbarrier::complete_tx::bytes [%0], [%1], %2, [%3];"
        :: "r"(dst), "l"(src), "r"(bytes), "r"(mbar) : "memory");
}
#define MBAR_INIT(mb, c)  asm volatile("mbarrier.init.shared.b64 [%0], %1;" :: "r"(mb), "r"(c) : "memory")
#define MBAR_EXPECT(mb, n) asm volatile("mbarrier.arrive.expect_tx.shared.b64 _, [%0], %1;" :: "r"(mb), "r"(n) : "memory")
#define MBAR_WAIT(mb, ph) do { \
    uint32_t _m = (mb), _p = (ph), _d; \
    asm volatile("{ .reg .pred p; mbarrier.try_wait.parity.acquire.cta.shared::cta.b64 p, [%1], %2; selp.b32 %0,1,0,p; }" \
        : "=r"(_d) : "r"(_m), "r"(_p) : "memory"); \
    if (!_d) { \
        asm volatile("{ .reg .pred P1;\nWL_%=:\n mbarrier.try_wait.parity.acquire.cta.shared::cta.b64 P1, [%0], %1, 0x989680;\n @P1 bra.uni WD_%=;\n bra.uni WL_%=;\nWD_%=:\n}" \
            :: "r"(_m), "r"(_p) : "memory"); \
    } } while (0)

// ================= K0: fp32 -> fp16 into tiled, pre-swizzled layout =================
// one thread = one 16B fp16 chunk (8 elems)
#define NX8  (MROWS*DIMV/8)     /* 524288 */
#define NW8  (DIMV*DIMV/8)      /* 131072 */
__global__ void kconv_all(const float* __restrict__ x, const float* __restrict__ Wz,
                          const float* __restrict__ Wza, const float* __restrict__ Wya)
{
    int i = blockIdx.x * blockDim.x + threadIdx.x;
    const float* src;
    __half* base;
    size_t soff, doff;
    if (i < NX8) {
        int r = i >> 7, c = i & 127;
        int kt = c >> 2, cc = c & 3;
        int T = (r >> 7)*32 + kt;
        src = x; soff = (size_t)r*DIMV + c*8;
        base = g_xf;
        doff = (size_t)T*8192 + SWZ64((uint32_t)(((r & 127) << 6) | (cc << 4)));
    } else {
        int e = i - NX8;
        int m = e >> 17;                 // 0:Wz 1:Wza 2:Wya
        e &= (NW8 - 1);
        int j = e >> 7, c = e & 127;
        int kt = c >> 2, cc = c & 3;
        int n;
        if (m == 0)      { src = Wz;  base = g_wzi; n = 2*j; }
        else if (m == 1) { src = Wza; base = g_wzi; n = 2*j + 1; }
        else             { src = Wya; base = g_wy;  n = j; }
        int T = (n >> 7)*32 + kt;        // 128-row tiles
        soff = (size_t)j*DIMV + c*8;
        doff = (size_t)T*8192 + SWZ64((uint32_t)(((n & 127) << 6) | (cc << 4)));
    }
    float4 v0 = ((const float4*)(src + soff))[0];
    float4 v1 = ((const float4*)(src + soff))[1];
    __half2 h0 = make_half2(__float2half(v0.x), __float2half(v0.y));
    __half2 h1 = make_half2(__float2half(v0.z), __float2half(v0.w));
    __half2 h2 = make_half2(__float2half(v1.x), __float2half(v1.y));
    __half2 h3 = make_half2(__float2half(v1.z), __float2half(v1.w));
    uint4 o;
    o.x = *(uint32_t*)&h0; o.y = *(uint32_t*)&h1;
    o.z = *(uint32_t*)&h2; o.w = *(uint32_t*)&h3;
    *(uint4*)((char*)base + doff) = o;
}

// ================= GEMM: BM=128, BN=128, BK=32, 256 thr (8 warps 4m x 2n), warp 32x64 =================
// 2 CTAs/SM; 3-stage pipeline; per stage: 8KB A bulk + 8KB B bulk
#define OFF_A  0
#define OFF_B  8192
#define STG    16384
#define NSTAGE 3
#define RED_OFF  (NSTAGE*STG)            /* 1KB reduction scratch */
#define MBAR_OFF (NSTAGE*STG + 1024)
#define GEMM_SMEM (NSTAGE*STG + 1024 + 8*NSTAGE)

__global__ void __launch_bounds__(256, 2)
kgemm_h(const float* __restrict__ bz, const float* __restrict__ bza)
{
    extern __shared__ char smem[];
    const uint32_t sb = smem_u32(smem);
    const uint32_t mb = sb + MBAR_OFF;
    const int tid = threadIdx.x;
    const int wid = tid >> 5, lane = tid & 31;
    const int wm = wid >> 1, wn = wid & 1;          // 4m x 2n warps
    const bool isA = blockIdx.x < 16;
    const int tI = isA ? blockIdx.x : (blockIdx.x - 16);
    const int r0 = blockIdx.y * 128;
    const char* Abase = (const char*)g_xf + (size_t)blockIdx.y * 32 * 8192;
    const char* Bbase = (isA ? (const char*)g_wzi : (const char*)g_wy) + (size_t)tI * 32 * 8192;

    float acc[2][8][4];
#pragma unroll
    for (int m = 0; m < 2; m++)
#pragma unroll
        for (int n = 0; n < 8; n++)
#pragma unroll
            for (int c = 0; c < 4; c++) acc[m][n][c] = 0.f;

    if (tid == 0) {
#pragma unroll
        for (int s = 0; s < NSTAGE; s++) MBAR_INIT(mb + 8*s, 1);
    }
    __syncthreads();

    if (tid == 0) {
#pragma unroll
        for (int s = 0; s < NSTAGE; s++) {
            MBAR_EXPECT(mb + 8*s, 16384u);
            bulkcp(sb + s*STG + OFF_A, Abase + (size_t)s*8192, 8192u, mb + 8*s);
            bulkcp(sb + s*STG + OFF_B, Bbase + (size_t)s*8192, 8192u, mb + 8*s);
        }
    }

    for (int it = 0; it < 32; it++) {
        int s = it % NSTAGE;
        MBAR_WAIT(mb + 8*s, (uint32_t)((it / NSTAGE) & 1));

        uint32_t stg = sb + s * STG;
#pragma unroll
        for (int kh = 0; kh < 2; kh++) {
            uint32_t af[2][4];
#pragma unroll
            for (int m = 0; m < 2; m++) {
                int row = wm*32 + m*16 + (lane & 15);
                uint32_t so = SWZ64((uint32_t)(row*64 + (kh*2 + (lane >> 4))*16));
                ldmx4(af[m], stg + OFF_A + so);
            }
#pragma unroll
            for (int p = 0; p < 4; p++) {
                int row = wn*64 + p*16 + (lane & 7) + ((lane >> 4) & 1) * 8;
                uint32_t so = SWZ64((uint32_t)(row*64 + (kh*2 + ((lane >> 3) & 1))*16));
                uint32_t bt[4];
                ldmx4(bt, stg + OFF_B + so);
#pragma unroll
                for (int m = 0; m < 2; m++) {
                    mma_f16(acc[m][2*p],   af[m], &bt[0]);
                    mma_f16(acc[m][2*p+1], af[m], &bt[2]);
                }
            }
        }
        __syncthreads();                 // all warps done reading stage s
        if (tid == 0 && it + NSTAGE < 32) {
            MBAR_EXPECT(mb + 8*s, 16384u);
            bulkcp(sb + s*STG + OFF_A, Abase + (size_t)(it+NSTAGE)*8192, 8192u, mb + 8*s);
            bulkcp(sb + s*STG + OFF_B, Bbase + (size_t)(it+NSTAGE)*8192, 8192u, mb + 8*s);
        }
    }

    if (!isA) {
        // ---- yact epilogue ----
        int nb = tI * 128;
#pragma unroll
        for (int m = 0; m < 2; m++) {
            int rowA = r0 + wm*32 + m*16 + (lane >> 2);
#pragma unroll
            for (int n = 0; n < 8; n++) {
                int col = nb + wn*64 + n*8 + (lane & 3)*2;
                *(float2*)(g_yact + (size_t)rowA*DIMV + col)     = make_float2(acc[m][n][0], acc[m][n][1]);
                *(float2*)(g_yact + (size_t)(rowA+8)*DIMV + col) = make_float2(acc[m][n][2], acc[m][n][3]);
            }
        }
        return;
    }

    // ---- z epilogue: z = (lin+bz)*silu(act+bza); masked colsums; zrows ----
    float* red = (float*)(smem + RED_OFF);          // [4][64]
    const int g = lane >> 2, q = lane & 3;
    const int bI = r0 >> 11;
    float zsum[8];
#pragma unroll
    for (int n = 0; n < 8; n++) {
        int jz = tI*64 + wn*32 + n*4 + q;           // z column 0..1023
        int h  = jz >> 7;
        float bzv = bz[jz], bzav = bza[jz];
        float s = 0.f;
#pragma unroll
        for (int m = 0; m < 2; m++) {
            int rowb = wm*32 + m*16 + g;
            float z0 = (acc[m][n][0] + bzv) * siluf(acc[m][n][1] + bzav);
            float z1 = (acc[m][n][2] + bzv) * siluf(acc[m][n][3] + bzav);
            int l0 = (r0 + rowb) & (Ldim-1);
            int l1 = (r0 + rowb + 8) & (Ldim-1);
            if (l0 > h) s += z0;
            if (l1 > h) s += z1;
            if (m == 0 && wm == 0 && ((r0 & (Ldim-1)) == 0))
                g_zrows[bI][g][jz] = z0;            // rows l=0..7
        }
        zsum[n] = s;
    }
#pragma unroll
    for (int n = 0; n < 8; n++) {
        for (int off = 4; off < 32; off <<= 1)
            zsum[n] += __shfl_xor_sync(0xffffffffu, zsum[n], off);
    }
    if (g == 0) {
#pragma unroll
        for (int n = 0; n < 8; n++)
            red[wm*64 + wn*32 + n*4 + q] = zsum[n];
    }
    __syncthreads();
    if (tid < 64) {
        float s = red[tid] + red[64 + tid] + red[128 + tid] + red[192 + tid];
        g_spart[r0 >> 7][tI*64 + tid] = s;
    }
}

// ================= K1a: dt projection (warp per row) =================
__global__ void k1_dt(const float* __restrict__ x, const float* __restrict__ Wdt,
                      const float* __restrict__ bdt, const float* __restrict__ lna)
{
    int gw   = (blockIdx.x * blockDim.x + threadIdx.x) >> 5;
    int lane = threadIdx.x & 31;
    if (gw >= MROWS) return;
    const float* xr = x + (size_t)gw * DIMV;
    float acc[NH];
#pragma unroll
    for (int h = 0; h < NH; h++) acc[h] = 0.f;
    for (int k = lane; k < DIMV; k += 32) {
        float xv = xr[k];
#pragma unroll
        for (int h = 0; h < NH; h++) acc[h] += xv * Wdt[h*DIMV + k];
    }
#pragma unroll
    for (int h = 0; h < NH; h++)
        for (int off = 16; off; off >>= 1)
            acc[h] += __shfl_xor_sync(0xffffffffu, acc[h], off);
    if (lane == 0) {
        int b = gw >> 11, l = gw & (Ldim-1);
#pragma unroll
        for (int h = 0; h < NH; h++) {
            float v  = acc[h] + bdt[h];
            float sp = fmaxf(v, 0.f) + log1pf(expf(-fabsf(v)));
            g_lda[b][h][l] = -expf(lna[h]) * sp;
        }
    }
}

// ================= K1b: inclusive scan + exp =================
__global__ void k1b_scan()
{
    int b = blockIdx.x >> 3, h = blockIdx.x & 7;
    int t = threadIdx.x;
    const float* src = g_lda[b][h];
    int base = t * 8;
    float v[8]; float s = 0.f;
#pragma unroll
    for (int u = 0; u < 8; u++) { v[u] = src[base+u]; s += v[u]; }
    __shared__ float sm[256];
    sm[t] = s; __syncthreads();
    for (int d = 1; d < 256; d <<= 1) {
        float add = (t >= d) ? sm[t-d] : 0.f;
        __syncthreads();
        sm[t] += add;
        __syncthreads();
    }
    float run = sm[t] - s;
#pragma unroll
    for (int u = 0; u < 8; u++) { run += v[u]; g_Acum[b][h][base+u] = expf(run); }
}

// ================= K3: per-(b,h) stats =================
__device__ __forceinline__ float blockSum128(float v, float* sm)
{
    for (int off = 16; off; off >>= 1) v += __shfl_xor_sync(0xffffffffu, v, off);
    int w = threadIdx.x >> 5;
    if ((threadIdx.x & 31) == 0) sm[w] = v;
    __syncthreads();
    float r = sm[0] + sm[1] + sm[2] + sm[3];
    __syncthreads();
    return r;
}

__global__ void k3_stats(const float* __restrict__ hidden, const float* __restrict__ gnw,
                         float* __restrict__ out, int writeHidden)
{
    int b = blockIdx.x >> 3, h = blockIdx.x & 7;
    int i = threadIdx.x;
    int col = h*INNER + i;
    float S = 0.f;
#pragma unroll 8
    for (int t = 0; t < MROWS/128/Bdim; t++)    // 16 tiles per batch
        S += g_spart[b*(MROWS/128/Bdim) + t][col];
    float c  = g_zrows[b][h][col];
    float tv = S + hidden[(b*NH+h)*INNER + i];

    __shared__ float sm[4];
    float mc = blockSum128(c,  sm) * (1.f/INNER);
    float mt = blockSum128(tv, sm) * (1.f/INNER);
    float dc = c - mc, dq = tv - mt;
    float vc = blockSum128(dc*dc, sm) * (1.f/INNER);
    float vt = blockSum128(dq*dq, sm) * (1.f/INNER);
    float cv = blockSum128(dc*dq, sm) * (1.f/INNER);
    if (i == 0) { g_vc[b][h]=vc; g_vt[b][h]=vt; g_cov[b][h]=cv; }
    float w = gnw[h];
    g_P[b][h][i] = dc * w;
    g_Q[b][h][i] = dq * w;
    if (writeHidden)
        out[(size_t)MROWS*DIMV + (b*NH+h)*INNER + i] = c + g_Acum[b][h][Ldim-1]*tv;
}

// ================= K4: rank-16 projections through W_y =================
__global__ void k4_proj(const float* __restrict__ Wy, const float* __restrict__ by,
                        const float* __restrict__ gnb)
{
    __shared__ float Ps[Bdim*NH*INNER];
    __shared__ float Qs[Bdim*NH*INNER];
    for (int idx = threadIdx.x; idx < Bdim*NH*INNER; idx += blockDim.x) {
        Ps[idx] = ((const float*)g_P)[idx];
        Qs[idx] = ((const float*)g_Q)[idx];
    }
    __syncthreads();
    int j    = (blockIdx.x * blockDim.x + threadIdx.x) >> 5;
    int lane = threadIdx.x & 31;
    if (j >= DIMV) return;
    const float* wrow = Wy + (size_t)j*DIMV;
    float gb = 0.f;
#pragma unroll
    for (int h = 0; h < NH; h++) {
        float aP0=0.f, aQ0=0.f, aP1=0.f, aQ1=0.f, aW=0.f;
#pragma unroll
        for (int kk = 0; kk < 4; kk++) {
            int ii = kk*32 + lane;
            float w = wrow[h*INNER + ii];
            aW  += w;
            aP0 += w * Ps[(0*NH+h)*INNER + ii];
            aQ0 += w * Qs[(0*NH+h)*INNER + ii];
            aP1 += w * Ps[(1*NH+h)*INNER + ii];
            aQ1 += w * Qs[(1*NH+h)*INNER + ii];
        }
        for (int off = 16; off; off >>= 1) {
            aP0 += __shfl_xor_sync(0xffffffffu, aP0, off);
            aQ0 += __shfl_xor_sync(0xffffffffu, aQ0, off);
            aP1 += __shfl_xor_sync(0xffffffffu, aP1, off);
            aQ1 += __shfl_xor_sync(0xffffffffu, aQ1, off);
            aW  += __shfl_xor_sync(0xffffffffu, aW,  off);
        }
        if (lane == 0) {
            g_PW[0][h][j] = aP0;  g_QW[0][h][j] = aQ0;
            g_PW[1][h][j] = aP1;  g_QW[1][h][j] = aQ1;
            gb += gnb[h] * aW;
        }
    }
    if (lane == 0) g_GW[j] = by[j] + gb;
}

// ================= K5: final combine =================
__global__ void k5_final(float* __restrict__ out, const float* __restrict__ bya)
{
    int r = blockIdx.x;
    int b = r >> 11, l = r & (Ldim-1);
    __shared__ float cP[NH], cQ[NH];
    if (threadIdx.x < NH) {
        int h = threadIdx.x;
        float A   = g_Acum[b][h][l];
        float var = g_vc[b][h] + 2.f*A*g_cov[b][h] + A*A*g_vt[b][h];
        float inv = rsqrtf(var + EPSV);
        cP[h] = inv;
        cQ[h] = A * inv;
    }
    __syncthreads();
    for (int j = threadIdx.x; j < DIMV; j += blockDim.x) {
        float y0 = g_GW[j];
#pragma unroll
        for (int h = 0; h < NH; h++)
            y0 += cP[h]*g_PW[b][h][j] + cQ[h]*g_QW[b][h][j];
        float ya = g_yact[(size_t)r*DIMV + j] + bya[j];
        out[(size_t)r*DIMV + j] = y0 * siluf(ya);
    }
}

// ================= launch =================
extern "C" void kernel_launch(void* const* d_in, const int* in_sizes, int n_in,
                              void* d_out, int out_size)
{
    const float* x    = (const float*)d_in[0];
    const float* hid  = (const float*)d_in[1];
    const float* W_z  = (const float*)d_in[2];
    const float* b_z  = (const float*)d_in[3];
    const float* W_za = (const float*)d_in[4];
    const float* b_za = (const float*)d_in[5];
    const float* W_y  = (const float*)d_in[6];
    const float* b_y  = (const float*)d_in[7];
    const float* W_ya = (const float*)d_in[8];
    const float* b_ya = (const float*)d_in[9];
    const float* W_dt = (const float*)d_in[10];
    const float* b_dt = (const float*)d_in[11];
    const float* ln_a = (const float*)d_in[12];
    const float* gn_w = (const float*)d_in[13];
    const float* gn_b = (const float*)d_in[14];
    float* out = (float*)d_out;
    int writeHidden = (out_size >= MROWS*DIMV + Bdim*NH*INNER) ? 1 : 0;

    cudaFuncSetAttribute(kgemm_h, cudaFuncAttributeMaxDynamicSharedMemorySize, GEMM_SMEM);

    const int NTOT = NX8 + 3*NW8;               // 917504
    kconv_all<<<NTOT/256, 256>>>(x, W_z, W_za, W_ya);

    k1_dt<<<MROWS/8, 256>>>(x, W_dt, b_dt, ln_a);

    dim3 gg(24, MROWS/128);                     // x: 16 z-blocks + 8 yact-blocks
    kgemm_h<<<gg, 256, GEMM_SMEM>>>(b_z, b_za);

    k1b_scan<<<Bdim*NH, 256>>>();
    k3_stats<<<Bdim*NH, INNER>>>(hid, gn_w, out, writeHidden);
    k4_proj<<<DIMV/8, 256>>>(W_y, b_y, gn_b);
    k5_final<<<MROWS, 256>>>(out, b_ya);
}